// round 1
// baseline (speedup 1.0000x reference)
#include <cuda_runtime.h>
#include <cuda_bf16.h>
#include <math.h>

#define N 8192
#define D 128
#define NEG_BIG 1000000.0f

// ---------------- scratch (no allocation allowed) ----------------
__device__ float g_q[N * D];
__device__ float g_k[N * D];
__device__ float g_v[N * D];
__device__ float g_m[N * D];
__device__ float g_h[N * D];

// ---------------- generic 128-wide GEMM: C = act(A[N,128] @ W[128,128] + b) ----------------
// grid.x = N/32 blocks, 128 threads. Thread j owns output column j for 32 rows.
__global__ void __launch_bounds__(128) gemm128_kernel(
    const float* __restrict__ A, const float* __restrict__ W,
    const float* __restrict__ bias, float* __restrict__ C, int relu)
{
    __shared__ float Hs[32 * 128];
    const int j  = threadIdx.x;
    const int i0 = blockIdx.x * 32;

    for (int idx = j; idx < 32 * 128; idx += 128)
        Hs[idx] = A[(size_t)i0 * 128 + idx];
    __syncthreads();

    float acc[32];
#pragma unroll
    for (int i = 0; i < 32; i++) acc[i] = 0.f;

#pragma unroll 4
    for (int kk = 0; kk < 128; kk++) {
        const float w = W[kk * 128 + j];
#pragma unroll
        for (int i = 0; i < 32; i++)
            acc[i] += Hs[i * 128 + kk] * w;
    }

    const float b = bias ? bias[j] : 0.f;
#pragma unroll
    for (int i = 0; i < 32; i++) {
        float v = acc[i] + b;
        if (relu) v = fmaxf(v, 0.f);
        C[(size_t)(i0 + i) * 128 + j] = v;
    }
}

// ---------------- flash attention with adjacency mask ----------------
// grid.x = N/64 blocks, 256 threads. BM=BN=64, D=128.
// Thread layout: tx = tid%16, ty = tid/16.
//   Phase A (scores): thread computes S[ty*4+a][tx*4+b], a,b in 0..3
//   Phase C (PV):     thread accumulates O[ty*4+a][tx*8+b], a 0..3, b 0..7
#define QT_STR 68   // padded stride for transposed [128][64] tiles
#define PT_STR 68
#define SM_QT   0
#define SM_KT   (SM_QT + 128 * QT_STR)
#define SM_VS   (SM_KT + 128 * QT_STR)
#define SM_S    (SM_VS + 64 * 128)
#define SM_PT   (SM_S  + 64 * PT_STR)
#define SM_RM   (SM_PT + 64 * PT_STR)
#define SM_RL   (SM_RM + 64)
#define SM_SC   (SM_RL + 64)
#define SM_PMAX (SM_SC + 64)
#define SM_PSUM (SM_PMAX + 256)
#define SM_FLOATS (SM_PSUM + 256)
#define SMEM_BYTES (SM_FLOATS * 4)

__global__ void __launch_bounds__(256, 1) attn_kernel(
    const float* __restrict__ q, const float* __restrict__ kmat,
    const float* __restrict__ vmat, const int* __restrict__ adj,
    float* __restrict__ out)
{
    extern __shared__ float sm[];
    float* Qt   = sm + SM_QT;
    float* Kt   = sm + SM_KT;
    float* Vs   = sm + SM_VS;
    float* Ssm  = sm + SM_S;
    float* Pt   = sm + SM_PT;
    float* rm   = sm + SM_RM;
    float* rl   = sm + SM_RL;
    float* sc   = sm + SM_SC;
    float* pmax = sm + SM_PMAX;
    float* psum = sm + SM_PSUM;

    const int tid = threadIdx.x;
    const int tx = tid & 15;
    const int ty = tid >> 4;
    const int qbase = blockIdx.x * 64;
    const float NEG_INF = -__int_as_float(0x7f800000);

    // load Q tile transposed: Qt[kk][i]
    for (int idx = tid; idx < 64 * 128; idx += 256) {
        const int i = idx >> 7, kk = idx & 127;
        Qt[kk * QT_STR + i] = q[(size_t)(qbase + i) * 128 + kk];
    }
    if (tid < 64) { rm[tid] = NEG_INF; rl[tid] = 0.f; }

    float o[4][8];
#pragma unroll
    for (int a = 0; a < 4; a++)
#pragma unroll
        for (int b = 0; b < 8; b++) o[a][b] = 0.f;

    __syncthreads();

    for (int t0 = 0; t0 < N; t0 += 64) {
        // ---- load K (transposed) and V tiles ----
        for (int idx = tid; idx < 64 * 128; idx += 256) {
            const int r = idx >> 7, kk = idx & 127;
            const float kv = kmat[(size_t)(t0 + r) * 128 + kk];
            const float vv = vmat[(size_t)(t0 + r) * 128 + kk];
            Kt[kk * QT_STR + r] = kv;
            Vs[r * 128 + kk]    = vv;
        }
        __syncthreads();

        // ---- Phase A: S[64][64] = Q @ K^T ----
        float acc[4][4];
#pragma unroll
        for (int a = 0; a < 4; a++)
#pragma unroll
            for (int b = 0; b < 4; b++) acc[a][b] = 0.f;

#pragma unroll 4
        for (int kk = 0; kk < 128; kk++) {
            const float4 rq = *(const float4*)&Qt[kk * QT_STR + ty * 4];
            const float4 rk = *(const float4*)&Kt[kk * QT_STR + tx * 4];
            acc[0][0] += rq.x * rk.x; acc[0][1] += rq.x * rk.y;
            acc[0][2] += rq.x * rk.z; acc[0][3] += rq.x * rk.w;
            acc[1][0] += rq.y * rk.x; acc[1][1] += rq.y * rk.y;
            acc[1][2] += rq.y * rk.z; acc[1][3] += rq.y * rk.w;
            acc[2][0] += rq.z * rk.x; acc[2][1] += rq.z * rk.y;
            acc[2][2] += rq.z * rk.z; acc[2][3] += rq.z * rk.w;
            acc[3][0] += rq.w * rk.x; acc[3][1] += rq.w * rk.y;
            acc[3][2] += rq.w * rk.z; acc[3][3] += rq.w * rk.w;
        }

        // ---- mask with adjacency, write S to smem ----
#pragma unroll
        for (int a = 0; a < 4; a++) {
            const int gi = qbase + ty * 4 + a;
            const int4 ad = *(const int4*)&adj[(size_t)gi * N + t0 + tx * 4];
            float* srow = &Ssm[(ty * 4 + a) * PT_STR + tx * 4];
            srow[0] = acc[a][0] - (ad.x > 0 ? 0.f : NEG_BIG);
            srow[1] = acc[a][1] - (ad.y > 0 ? 0.f : NEG_BIG);
            srow[2] = acc[a][2] - (ad.z > 0 ? 0.f : NEG_BIG);
            srow[3] = acc[a][3] - (ad.w > 0 ? 0.f : NEG_BIG);
        }
        __syncthreads();

        // ---- Phase B: online softmax stats ----
        {   // partial row max: 4 threads per row, 16 cols each
            const int row = tid >> 2, part = tid & 3;
            float mx = NEG_INF;
            const float* srow = &Ssm[row * PT_STR + part * 16];
#pragma unroll
            for (int u = 0; u < 16; u++) mx = fmaxf(mx, srow[u]);
            pmax[row * 4 + part] = mx;
        }
        __syncthreads();
        if (tid < 64) {
            const float mt = fmaxf(fmaxf(pmax[tid * 4], pmax[tid * 4 + 1]),
                                   fmaxf(pmax[tid * 4 + 2], pmax[tid * 4 + 3]));
            const float mold = rm[tid];
            const float mnew = fmaxf(mold, mt);
            rm[tid] = mnew;
            sc[tid] = __expf(mold - mnew);
        }
        __syncthreads();
        {   // exponentials, write P transposed, partial sums
            const int row = tid >> 2, part = tid & 3;
            const float mnew = rm[row];
            float s = 0.f;
#pragma unroll
            for (int u = 0; u < 16; u++) {
                const int jj = part * 16 + u;
                const float p = __expf(Ssm[row * PT_STR + jj] - mnew);
                Pt[jj * PT_STR + row] = p;
                s += p;
            }
            psum[row * 4 + part] = s;
        }
        __syncthreads();
        if (tid < 64) {
            rl[tid] = rl[tid] * sc[tid] +
                      psum[tid * 4] + psum[tid * 4 + 1] +
                      psum[tid * 4 + 2] + psum[tid * 4 + 3];
        }

        // ---- Phase C: O = O*scale + P @ V ----
#pragma unroll
        for (int a = 0; a < 4; a++) {
            const float s = sc[ty * 4 + a];
#pragma unroll
            for (int b = 0; b < 8; b++) o[a][b] *= s;
        }

#pragma unroll 4
        for (int jj = 0; jj < 64; jj++) {
            const float4 p4 = *(const float4*)&Pt[jj * PT_STR + ty * 4];
            const float4 v0 = *(const float4*)&Vs[jj * 128 + tx * 8];
            const float4 v1 = *(const float4*)&Vs[jj * 128 + tx * 8 + 4];
            o[0][0] += p4.x * v0.x; o[0][1] += p4.x * v0.y;
            o[0][2] += p4.x * v0.z; o[0][3] += p4.x * v0.w;
            o[0][4] += p4.x * v1.x; o[0][5] += p4.x * v1.y;
            o[0][6] += p4.x * v1.z; o[0][7] += p4.x * v1.w;
            o[1][0] += p4.y * v0.x; o[1][1] += p4.y * v0.y;
            o[1][2] += p4.y * v0.z; o[1][3] += p4.y * v0.w;
            o[1][4] += p4.y * v1.x; o[1][5] += p4.y * v1.y;
            o[1][6] += p4.y * v1.z; o[1][7] += p4.y * v1.w;
            o[2][0] += p4.z * v0.x; o[2][1] += p4.z * v0.y;
            o[2][2] += p4.z * v0.z; o[2][3] += p4.z * v0.w;
            o[2][4] += p4.z * v1.x; o[2][5] += p4.z * v1.y;
            o[2][6] += p4.z * v1.z; o[2][7] += p4.z * v1.w;
            o[3][0] += p4.w * v0.x; o[3][1] += p4.w * v0.y;
            o[3][2] += p4.w * v0.z; o[3][3] += p4.w * v0.w;
            o[3][4] += p4.w * v1.x; o[3][5] += p4.w * v1.y;
            o[3][6] += p4.w * v1.z; o[3][7] += p4.w * v1.w;
        }
        __syncthreads();   // protect Kt/Vs/Ssm/Pt before next tile
    }

    // ---- epilogue: divide by row sums, write out ----
#pragma unroll
    for (int a = 0; a < 4; a++) {
        const float inv = 1.f / rl[ty * 4 + a];
        const int gi = qbase + ty * 4 + a;
#pragma unroll
        for (int b = 0; b < 8; b++)
            out[(size_t)gi * 128 + tx * 8 + b] = o[a][b] * inv;
    }
}

// ---------------- launch ----------------
extern "C" void kernel_launch(void* const* d_in, const int* in_sizes, int n_in,
                              void* d_out, int out_size)
{
    const float* H  = (const float*)d_in[0];
    const int*   adj = (const int*)d_in[1];
    const float* Wq = (const float*)d_in[2];
    const float* Wk = (const float*)d_in[3];
    const float* Wv = (const float*)d_in[4];
    const float* W1 = (const float*)d_in[5];
    const float* b1 = (const float*)d_in[6];
    const float* W2 = (const float*)d_in[7];
    const float* b2 = (const float*)d_in[8];
    float* out = (float*)d_out;

    float *q, *k, *v, *m, *h;
    cudaGetSymbolAddress((void**)&q, g_q);
    cudaGetSymbolAddress((void**)&k, g_k);
    cudaGetSymbolAddress((void**)&v, g_v);
    cudaGetSymbolAddress((void**)&m, g_m);
    cudaGetSymbolAddress((void**)&h, g_h);

    cudaFuncSetAttribute(attn_kernel,
                         cudaFuncAttributeMaxDynamicSharedMemorySize, SMEM_BYTES);

    gemm128_kernel<<<N / 32, 128>>>(H, Wq, nullptr, q, 0);
    gemm128_kernel<<<N / 32, 128>>>(H, Wk, nullptr, k, 0);
    gemm128_kernel<<<N / 32, 128>>>(H, Wv, nullptr, v, 0);

    attn_kernel<<<N / 64, 256, SMEM_BYTES>>>(q, k, v, adj, m);

    gemm128_kernel<<<N / 32, 128>>>(m, W1, b1, h, 1);
    gemm128_kernel<<<N / 32, 128>>>(h, W2, b2, out, 1);
}

// round 3
// speedup vs baseline: 2.9433x; 2.9433x over previous
#include <cuda_runtime.h>
#include <cuda_bf16.h>
#include <cstdint>

#define NTOK 8192
#define DH   128

// ---------------- scratch ----------------
__device__ float g_q[NTOK * DH];
__device__ float g_k[NTOK * DH];
__device__ float g_v[NTOK * DH];
__device__ float g_vt[DH * NTOK];       // V transposed [d][t]
__device__ float g_mp[2 * NTOK * DH];   // split partial numerators
__device__ float g_lp[2 * NTOK];        // split partial denominators
__device__ float g_m[NTOK * DH];
__device__ float g_h[NTOK * DH];

// ---------------- warp-MMA helpers (sm_100-safe: no 'a' features) ----------------
__device__ __forceinline__ uint32_t smem_u32(const void* p) {
    uint32_t a;
    asm("{ .reg .u64 t; cvta.to.shared.u64 t, %1; cvt.u32.u64 %0, t; }" : "=r"(a) : "l"(p));
    return a;
}
__device__ __forceinline__ void ldm4(uint32_t addr, uint32_t r[4]) {
    asm volatile("ldmatrix.sync.aligned.m8n8.x4.shared.b16 {%0,%1,%2,%3}, [%4];"
                 : "=r"(r[0]), "=r"(r[1]), "=r"(r[2]), "=r"(r[3]) : "r"(addr));
}
__device__ __forceinline__ void mma16816(float c[4], uint32_t a0, uint32_t a1,
                                         uint32_t a2, uint32_t a3,
                                         uint32_t b0, uint32_t b1) {
    asm volatile("mma.sync.aligned.m16n8k16.row.col.f32.bf16.bf16.f32 "
                 "{%0,%1,%2,%3}, {%4,%5,%6,%7}, {%8,%9}, {%0,%1,%2,%3};"
                 : "+f"(c[0]), "+f"(c[1]), "+f"(c[2]), "+f"(c[3])
                 : "r"(a0), "r"(a1), "r"(a2), "r"(a3), "r"(b0), "r"(b1));
}
__device__ __forceinline__ uint32_t pkbf(float a, float b) {
    __nv_bfloat162 t = __floats2bfloat162_rn(a, b);
    return *reinterpret_cast<uint32_t*>(&t);
}

// split fp32 tile -> bf16 hi/lo, padded row-major
// rows*cols/4 float4's, 256 threads
__device__ __forceinline__ void ldcvt(const float* __restrict__ g, int rows, size_t rstride,
                                      int cols, __nv_bfloat16* hi, __nv_bfloat16* lo,
                                      int pad, int tid) {
    const int c4n = cols >> 2;
    const int tot = rows * c4n;
    for (int idx = tid; idx < tot; idx += 256) {
        const int row = idx / c4n, c4 = idx - row * c4n;
        float4 v = *(const float4*)(g + (size_t)row * rstride + c4 * 4);
        __nv_bfloat16 h0 = __float2bfloat16(v.x), h1 = __float2bfloat16(v.y);
        __nv_bfloat16 h2 = __float2bfloat16(v.z), h3 = __float2bfloat16(v.w);
        float l0 = v.x - __bfloat162float(h0), l1 = v.y - __bfloat162float(h1);
        float l2 = v.z - __bfloat162float(h2), l3 = v.w - __bfloat162float(h3);
        const int o = row * pad + c4 * 4;
        __nv_bfloat162 hv0 = __halves2bfloat162(h0, h1), hv1 = __halves2bfloat162(h2, h3);
        *(uint2*)(hi + o) = make_uint2(*(uint32_t*)&hv0, *(uint32_t*)&hv1);
        *(uint2*)(lo + o) = make_uint2(pkbf(l0, l1), pkbf(l2, l3));
    }
}

// ---------------- fused attention ----------------
#define PADQ 136
#define PADV 72
#define SQH 0
#define SQL (SQH + 128 * PADQ)          // elements (bf16)
#define SKH (SQL + 128 * PADQ)
#define SKL (SKH + 64 * PADQ)
#define SVH (SKL + 64 * PADQ)
#define SVL (SVH + 128 * PADV)
#define SM_ELEMS (SVL + 128 * PADV)
#define SM_BYTES (SM_ELEMS * 2)         // 141312

__global__ void __launch_bounds__(256, 1) attn_kernel(
    const float* __restrict__ q, const float* __restrict__ k,
    const float* __restrict__ vt, const int* __restrict__ adj,
    float* __restrict__ mp, float* __restrict__ lp)
{
    extern __shared__ __nv_bfloat16 sm[];
    const uint32_t sb = smem_u32(sm);
    const int tid = threadIdx.x;
    const int wid = tid >> 5, lid = tid & 31;
    const int wrow = wid * 16;
    const int qbase = blockIdx.x * 128;
    const int split = blockIdx.y;
    const int tstart = split * (NTOK / 2);

    // ldmatrix per-lane row/col offsets
    const int lrow = lid & 15, lcol = (lid >> 4) * 8;
    const uint32_t qoff = sb + (SQH + (wrow + lrow) * PADQ + lcol) * 2;
    const uint32_t qloff = qoff + (SQL - SQH) * 2;
    const uint32_t koff = sb + (SKH + lrow * PADQ + lcol) * 2;
    const uint32_t kloff = koff + (SKL - SKH) * 2;
    const uint32_t voff = sb + (SVH + lrow * PADV + lcol) * 2;
    const uint32_t vloff = voff + (SVL - SVH) * 2;

    // fragment row ids for this thread
    const int fr0 = wrow + (lid >> 2);      // local rows
    const int r0g = qbase + fr0;            // global q rows
    const int r1g = r0g + 8;
    const int cq = 2 * (lid & 3);           // fragment col base within 8-block

    ldcvt(q + (size_t)qbase * DH, 128, DH, DH, sm + SQH, sm + SQL, PADQ, tid);

    float oacc[16][4];
#pragma unroll
    for (int i = 0; i < 16; i++)
#pragma unroll
        for (int j = 0; j < 4; j++) oacc[i][j] = 0.f;
    float rs0 = 0.f, rs1 = 0.f;

    __syncthreads();

    for (int it = 0; it < (NTOK / 2) / 64; it++) {
        const int t0 = tstart + it * 64;
        if (it) __syncthreads();
        ldcvt(k + (size_t)t0 * DH, 64, DH, DH, sm + SKH, sm + SKL, PADQ, tid);
        ldcvt(vt + t0, 128, NTOK, 64, sm + SVH, sm + SVL, PADV, tid);
        __syncthreads();

        // ---- S = Q K^T (3-term bf16 split) ----
        float sacc[8][4];
#pragma unroll
        for (int i = 0; i < 8; i++)
#pragma unroll
            for (int j = 0; j < 4; j++) sacc[i][j] = 0.f;

#pragma unroll
        for (int kc = 0; kc < 8; kc++) {
            uint32_t qh[4], ql[4];
            ldm4(qoff + kc * 32, qh);    // 16 elems * 2B
            ldm4(qloff + kc * 32, ql);
#pragma unroll
            for (int nb2 = 0; nb2 < 4; nb2++) {
                uint32_t kh[4], kl[4];
                ldm4(koff + (nb2 * 16 * PADQ + kc * 16) * 2, kh);
                ldm4(kloff + (nb2 * 16 * PADQ + kc * 16) * 2, kl);
                mma16816(sacc[2 * nb2],     qh[0], qh[1], qh[2], qh[3], kh[0], kh[2]);
                mma16816(sacc[2 * nb2 + 1], qh[0], qh[1], qh[2], qh[3], kh[1], kh[3]);
                mma16816(sacc[2 * nb2],     qh[0], qh[1], qh[2], qh[3], kl[0], kl[2]);
                mma16816(sacc[2 * nb2 + 1], qh[0], qh[1], qh[2], qh[3], kl[1], kl[3]);
                mma16816(sacc[2 * nb2],     ql[0], ql[1], ql[2], ql[3], kh[0], kh[2]);
                mma16816(sacc[2 * nb2 + 1], ql[0], ql[1], ql[2], ql[3], kh[1], kh[3]);
            }
        }

        // ---- mask + exp -> P fragments (hi/lo) ----
        uint32_t ph[8][2], pl[8][2];
#pragma unroll
        for (int nb = 0; nb < 8; nb++) {
            const int col = t0 + nb * 8 + cq;
            const int2 a0 = *(const int2*)(adj + (size_t)r0g * NTOK + col);
            const int2 a1 = *(const int2*)(adj + (size_t)r1g * NTOK + col);
            float p00 = (a0.x > 0) ? __expf(sacc[nb][0]) : 0.f;
            float p01 = (a0.y > 0) ? __expf(sacc[nb][1]) : 0.f;
            float p10 = (a1.x > 0) ? __expf(sacc[nb][2]) : 0.f;
            float p11 = (a1.y > 0) ? __expf(sacc[nb][3]) : 0.f;
            rs0 += p00 + p01;
            rs1 += p10 + p11;
            __nv_bfloat16 h00 = __float2bfloat16(p00), h01 = __float2bfloat16(p01);
            __nv_bfloat16 h10 = __float2bfloat16(p10), h11 = __float2bfloat16(p11);
            __nv_bfloat162 hv0 = __halves2bfloat162(h00, h01);
            __nv_bfloat162 hv1 = __halves2bfloat162(h10, h11);
            ph[nb][0] = *(uint32_t*)&hv0;
            ph[nb][1] = *(uint32_t*)&hv1;
            pl[nb][0] = pkbf(p00 - __bfloat162float(h00), p01 - __bfloat162float(h01));
            pl[nb][1] = pkbf(p10 - __bfloat162float(h10), p11 - __bfloat162float(h11));
        }

        // ---- O += P V (3-term split) ----
#pragma unroll
        for (int kc2 = 0; kc2 < 4; kc2++) {
            const uint32_t ah0 = ph[2 * kc2][0], ah1 = ph[2 * kc2][1];
            const uint32_t ah2 = ph[2 * kc2 + 1][0], ah3 = ph[2 * kc2 + 1][1];
            const uint32_t al0 = pl[2 * kc2][0], al1 = pl[2 * kc2][1];
            const uint32_t al2 = pl[2 * kc2 + 1][0], al3 = pl[2 * kc2 + 1][1];
#pragma unroll
            for (int db2 = 0; db2 < 8; db2++) {
                uint32_t vh[4], vl[4];
                ldm4(voff + (db2 * 16 * PADV + kc2 * 16) * 2, vh);
                ldm4(vloff + (db2 * 16 * PADV + kc2 * 16) * 2, vl);
                mma16816(oacc[2 * db2],     ah0, ah1, ah2, ah3, vh[0], vh[2]);
                mma16816(oacc[2 * db2 + 1], ah0, ah1, ah2, ah3, vh[1], vh[3]);
                mma16816(oacc[2 * db2],     ah0, ah1, ah2, ah3, vl[0], vl[2]);
                mma16816(oacc[2 * db2 + 1], ah0, ah1, ah2, ah3, vl[1], vl[3]);
                mma16816(oacc[2 * db2],     al0, al1, al2, al3, vh[0], vh[2]);
                mma16816(oacc[2 * db2 + 1], al0, al1, al2, al3, vh[1], vh[3]);
            }
        }
    }

    // ---- row sums: reduce within quad ----
    rs0 += __shfl_xor_sync(0xffffffff, rs0, 1);
    rs0 += __shfl_xor_sync(0xffffffff, rs0, 2);
    rs1 += __shfl_xor_sync(0xffffffff, rs1, 1);
    rs1 += __shfl_xor_sync(0xffffffff, rs1, 2);
    if ((lid & 3) == 0) {
        lp[(size_t)split * NTOK + r0g] = rs0;
        lp[(size_t)split * NTOK + r1g] = rs1;
    }

    // ---- store O partials ----
    float* mp0 = mp + ((size_t)split * NTOK + r0g) * DH;
    float* mp1 = mp + ((size_t)split * NTOK + r1g) * DH;
#pragma unroll
    for (int db = 0; db < 16; db++) {
        const int c = db * 8 + cq;
        *(float2*)(mp0 + c) = make_float2(oacc[db][0], oacc[db][1]);
        *(float2*)(mp1 + c) = make_float2(oacc[db][2], oacc[db][3]);
    }
}

// ---------------- fp32 GEMM: C[8192,128] = act(A @ W + b) ----------------
__global__ void __launch_bounds__(256) gemm2_kernel(
    const float* __restrict__ A, const float* __restrict__ W,
    const float* __restrict__ bias, float* __restrict__ C, int relu)
{
    extern __shared__ float smf[];
    float* As = smf;
    float* Ws = smf + 64 * 128;
    const int tid = threadIdx.x;
    const int tx = tid & 15, ty = tid >> 4;
    const int r0 = blockIdx.x * 64;

    for (int idx = tid; idx < 64 * 32; idx += 256) {
        int row = idx >> 5, f4 = idx & 31;
        ((float4*)(As + row * 128))[f4] = ((const float4*)(A + (size_t)(r0 + row) * 128))[f4];
    }
    for (int idx = tid; idx < 128 * 32; idx += 256) {
        int row = idx >> 5, f4 = idx & 31;
        ((float4*)(Ws + row * 128))[f4] = ((const float4*)(W + row * 128))[f4];
    }
    __syncthreads();

    float acc[4][8];
#pragma unroll
    for (int i = 0; i < 4; i++)
#pragma unroll
        for (int j = 0; j < 8; j++) acc[i][j] = 0.f;

#pragma unroll 4
    for (int kk = 0; kk < 128; kk++) {
        float a0 = As[(ty * 4 + 0) * 128 + kk];
        float a1 = As[(ty * 4 + 1) * 128 + kk];
        float a2 = As[(ty * 4 + 2) * 128 + kk];
        float a3 = As[(ty * 4 + 3) * 128 + kk];
        float4 w0 = ((float4*)(Ws + kk * 128))[tx * 2];
        float4 w1 = ((float4*)(Ws + kk * 128))[tx * 2 + 1];
        acc[0][0] += a0 * w0.x; acc[0][1] += a0 * w0.y; acc[0][2] += a0 * w0.z; acc[0][3] += a0 * w0.w;
        acc[0][4] += a0 * w1.x; acc[0][5] += a0 * w1.y; acc[0][6] += a0 * w1.z; acc[0][7] += a0 * w1.w;
        acc[1][0] += a1 * w0.x; acc[1][1] += a1 * w0.y; acc[1][2] += a1 * w0.z; acc[1][3] += a1 * w0.w;
        acc[1][4] += a1 * w1.x; acc[1][5] += a1 * w1.y; acc[1][6] += a1 * w1.z; acc[1][7] += a1 * w1.w;
        acc[2][0] += a2 * w0.x; acc[2][1] += a2 * w0.y; acc[2][2] += a2 * w0.z; acc[2][3] += a2 * w0.w;
        acc[2][4] += a2 * w1.x; acc[2][5] += a2 * w1.y; acc[2][6] += a2 * w1.z; acc[2][7] += a2 * w1.w;
        acc[3][0] += a3 * w0.x; acc[3][1] += a3 * w0.y; acc[3][2] += a3 * w0.z; acc[3][3] += a3 * w0.w;
        acc[3][4] += a3 * w1.x; acc[3][5] += a3 * w1.y; acc[3][6] += a3 * w1.z; acc[3][7] += a3 * w1.w;
    }

#pragma unroll
    for (int i = 0; i < 4; i++) {
        float* crow = C + (size_t)(r0 + ty * 4 + i) * 128 + tx * 8;
#pragma unroll
        for (int j = 0; j < 8; j++) {
            float v = acc[i][j] + (bias ? bias[tx * 8 + j] : 0.f);
            if (relu) v = fmaxf(v, 0.f);
            crow[j] = v;
        }
    }
}

// ---------------- V transpose ----------------
__global__ void __launch_bounds__(256) transpose_kernel(
    const float* __restrict__ v, float* __restrict__ vtout)
{
    __shared__ float ts[32][33];
    const int tb0 = blockIdx.x * 32, db0 = blockIdx.y * 32;
    const int x = threadIdx.x & 31, y = threadIdx.x >> 5;
#pragma unroll
    for (int i = 0; i < 32; i += 8)
        ts[y + i][x] = v[(size_t)(tb0 + y + i) * DH + db0 + x];
    __syncthreads();
#pragma unroll
    for (int i = 0; i < 32; i += 8)
        vtout[(size_t)(db0 + y + i) * NTOK + tb0 + x] = ts[x][y + i];
}

// ---------------- combine splits ----------------
__global__ void __launch_bounds__(256) combine_kernel(
    const float* __restrict__ mp, const float* __restrict__ lp, float* __restrict__ out)
{
    const int idx = blockIdx.x * 256 + threadIdx.x;
    const int qrow = idx >> 7;
    const float L = lp[qrow] + lp[NTOK + qrow];
    out[idx] = (mp[idx] + mp[NTOK * DH + idx]) / L;
}

// ---------------- launch ----------------
extern "C" void kernel_launch(void* const* d_in, const int* in_sizes, int n_in,
                              void* d_out, int out_size)
{
    const float* H   = (const float*)d_in[0];
    const int*   adj = (const int*)d_in[1];
    const float* Wq  = (const float*)d_in[2];
    const float* Wk  = (const float*)d_in[3];
    const float* Wv  = (const float*)d_in[4];
    const float* W1  = (const float*)d_in[5];
    const float* b1  = (const float*)d_in[6];
    const float* W2  = (const float*)d_in[7];
    const float* b2  = (const float*)d_in[8];
    float* out = (float*)d_out;

    float *q, *k, *v, *vt, *mp, *lpd, *m, *h;
    cudaGetSymbolAddress((void**)&q,  g_q);
    cudaGetSymbolAddress((void**)&k,  g_k);
    cudaGetSymbolAddress((void**)&v,  g_v);
    cudaGetSymbolAddress((void**)&vt, g_vt);
    cudaGetSymbolAddress((void**)&mp, g_mp);
    cudaGetSymbolAddress((void**)&lpd, g_lp);
    cudaGetSymbolAddress((void**)&m,  g_m);
    cudaGetSymbolAddress((void**)&h,  g_h);

    cudaFuncSetAttribute(attn_kernel, cudaFuncAttributeMaxDynamicSharedMemorySize, SM_BYTES);
    cudaFuncSetAttribute(gemm2_kernel, cudaFuncAttributeMaxDynamicSharedMemorySize, 96 * 1024);

    const int gsm = 96 * 1024;
    gemm2_kernel<<<NTOK / 64, 256, gsm>>>(H, Wq, nullptr, q, 0);
    gemm2_kernel<<<NTOK / 64, 256, gsm>>>(H, Wk, nullptr, k, 0);
    gemm2_kernel<<<NTOK / 64, 256, gsm>>>(H, Wv, nullptr, v, 0);

    transpose_kernel<<<dim3(NTOK / 32, DH / 32), 256>>>(v, vt);

    attn_kernel<<<dim3(NTOK / 128, 2), 256, SM_BYTES>>>(q, k, vt, adj, mp, lpd);

    combine_kernel<<<NTOK * DH / 256, 256>>>(mp, lpd, m);

    gemm2_kernel<<<NTOK / 64, 256, gsm>>>(m, W1, b1, h, 1);
    gemm2_kernel<<<NTOK / 64, 256, gsm>>>(h, W2, b2, out, 1);
}

// round 6
// speedup vs baseline: 4.0203x; 1.3659x over previous
#include <cuda_runtime.h>
#include <cuda_bf16.h>
#include <cuda_fp16.h>
#include <cstdint>

#define NTOK 8192
#define DH   128

// ---------------- scratch ----------------
__device__ float g_q[NTOK * DH];
__device__ float g_k[NTOK * DH];
__device__ float g_v[NTOK * DH];
__device__ __nv_bfloat16 g_qh[NTOK * DH];
__device__ __nv_bfloat16 g_ql[NTOK * DH];
__device__ __nv_bfloat16 g_kh[NTOK * DH];
__device__ __nv_bfloat16 g_kl[NTOK * DH];
__device__ __half g_vth[DH * NTOK];
__device__ __half g_vtl[DH * NTOK];
__device__ float g_mp[2 * NTOK * DH];
__device__ float g_lp[4 * NTOK];       // [split][rs | m][row]
__device__ float g_m[NTOK * DH];
__device__ float g_h[NTOK * DH];

// ---------------- helpers ----------------
__device__ __forceinline__ uint32_t smem_u32(const void* p) {
    uint32_t a;
    asm("{ .reg .u64 t; cvta.to.shared.u64 t, %1; cvt.u32.u64 %0, t; }" : "=r"(a) : "l"(p));
    return a;
}
__device__ __forceinline__ void cpa16(uint32_t dst, const void* src) {
    asm volatile("cp.async.cg.shared.global [%0], [%1], 16;" :: "r"(dst), "l"(src));
}
__device__ __forceinline__ void cpa_commit() {
    asm volatile("cp.async.commit_group;" ::: "memory");
}
__device__ __forceinline__ void cpa_wait0() {
    asm volatile("cp.async.wait_group 0;" ::: "memory");
}
__device__ __forceinline__ void ldm4(uint32_t addr, uint32_t r[4]) {
    asm volatile("ldmatrix.sync.aligned.m8n8.x4.shared.b16 {%0,%1,%2,%3}, [%4];"
                 : "=r"(r[0]), "=r"(r[1]), "=r"(r[2]), "=r"(r[3]) : "r"(addr));
}
__device__ __forceinline__ void mma_bf16(float c[4], uint32_t a0, uint32_t a1,
                                         uint32_t a2, uint32_t a3,
                                         uint32_t b0, uint32_t b1) {
    asm volatile("mma.sync.aligned.m16n8k16.row.col.f32.bf16.bf16.f32 "
                 "{%0,%1,%2,%3}, {%4,%5,%6,%7}, {%8,%9}, {%0,%1,%2,%3};"
                 : "+f"(c[0]), "+f"(c[1]), "+f"(c[2]), "+f"(c[3])
                 : "r"(a0), "r"(a1), "r"(a2), "r"(a3), "r"(b0), "r"(b1));
}
__device__ __forceinline__ void mma_f16(float c[4], uint32_t a0, uint32_t a1,
                                        uint32_t a2, uint32_t a3,
                                        uint32_t b0, uint32_t b1) {
    asm volatile("mma.sync.aligned.m16n8k16.row.col.f32.f16.f16.f32 "
                 "{%0,%1,%2,%3}, {%4,%5,%6,%7}, {%8,%9}, {%0,%1,%2,%3};"
                 : "+f"(c[0]), "+f"(c[1]), "+f"(c[2]), "+f"(c[3])
                 : "r"(a0), "r"(a1), "r"(a2), "r"(a3), "r"(b0), "r"(b1));
}
__device__ __forceinline__ uint32_t pkbf(float a, float b) {
    __nv_bfloat162 t = __floats2bfloat162_rn(a, b);
    return *reinterpret_cast<uint32_t*>(&t);
}

// ---------------- pre-convert kernels ----------------
__global__ void __launch_bounds__(256) qkconv_kernel(
    const float* __restrict__ q, const float* __restrict__ k,
    __nv_bfloat16* __restrict__ qh, __nv_bfloat16* __restrict__ ql,
    __nv_bfloat16* __restrict__ kh, __nv_bfloat16* __restrict__ kl)
{
    const int idx = blockIdx.x * 256 + threadIdx.x;       // float4 index
    const float* src = blockIdx.y ? k : q;
    __nv_bfloat16* dh = blockIdx.y ? kh : qh;
    __nv_bfloat16* dl = blockIdx.y ? kl : ql;
    float4 v = ((const float4*)src)[idx];
    __nv_bfloat16 h0 = __float2bfloat16(v.x), h1 = __float2bfloat16(v.y);
    __nv_bfloat16 h2 = __float2bfloat16(v.z), h3 = __float2bfloat16(v.w);
    __nv_bfloat162 hv0 = __halves2bfloat162(h0, h1), hv1 = __halves2bfloat162(h2, h3);
    ((uint2*)dh)[idx] = make_uint2(*(uint32_t*)&hv0, *(uint32_t*)&hv1);
    ((uint2*)dl)[idx] = make_uint2(pkbf(v.x - __bfloat162float(h0), v.y - __bfloat162float(h1)),
                                   pkbf(v.z - __bfloat162float(h2), v.w - __bfloat162float(h3)));
}

__global__ void __launch_bounds__(256) vtconv_kernel(
    const float* __restrict__ v, __half* __restrict__ vth, __half* __restrict__ vtl)
{
    __shared__ float ts[32][33];
    const int tb0 = blockIdx.x * 32, db0 = blockIdx.y * 32;
    const int x = threadIdx.x & 31, y = threadIdx.x >> 5;
#pragma unroll
    for (int i = 0; i < 32; i += 8)
        ts[y + i][x] = v[(size_t)(tb0 + y + i) * DH + db0 + x];
    __syncthreads();
#pragma unroll
    for (int i = 0; i < 32; i += 8) {
        float val = ts[x][y + i];
        __half h = __float2half_rn(val);
        __half l = __float2half_rn(val - __half2float(h));
        vth[(size_t)(db0 + y + i) * NTOK + tb0 + x] = h;
        vtl[(size_t)(db0 + y + i) * NTOK + tb0 + x] = l;
    }
}

// ---------------- fused attention ----------------
#define QH_OFF 0
#define QL_OFF 17408
#define KH_OFF 34816
#define KL_OFF 52224
#define VH_OFF 69632
#define VL_OFF 88064
#define ATT_SMEM 106496
#define KPAD 272
#define VPAD 144
#define MNEG  -1e30f    // masked-score sentinel
#define MINIT -1e29f    // running-max init (> MNEG so all-masked tiles yield p=0)

__global__ void __launch_bounds__(128, 2) attn_kernel(
    const __nv_bfloat16* __restrict__ qhg, const __nv_bfloat16* __restrict__ qlg,
    const __nv_bfloat16* __restrict__ khg, const __nv_bfloat16* __restrict__ klg,
    const __half* __restrict__ vthg, const __half* __restrict__ vtlg,
    const int* __restrict__ adj, float* __restrict__ mp, float* __restrict__ lp)
{
    extern __shared__ char smc[];
    const uint32_t sb = smem_u32(smc);
    const int tid = threadIdx.x;
    const int wid = tid >> 5, lid = tid & 31;
    const int wrow = wid * 16;
    const int qbase = blockIdx.x * 64;
    const int split = blockIdx.y;
    const int tstart = split * (NTOK / 2);

    const int lrow = lid & 15, lcol = (lid >> 4) * 8;
    const uint32_t qoff = sb + QH_OFF + (wrow + lrow) * KPAD + lcol * 2;
    const uint32_t koff = sb + KH_OFF + lrow * KPAD + lcol * 2;
    const uint32_t voff = sb + VH_OFF + lrow * VPAD + lcol * 2;

    const int fr0 = wrow + (lid >> 2);
    const int r0g = qbase + fr0;
    const int r1g = r0g + 8;
    const int cq = 2 * (lid & 3);

    // Q tile (its own commit group; first tile's wait covers it)
#pragma unroll
    for (int i = 0; i < 8; i++) {
        const int idx = tid + i * 128;
        const int r = idx >> 4, c = idx & 15;
        cpa16(sb + QH_OFF + r * KPAD + c * 16, qhg + (size_t)(qbase + r) * DH + c * 8);
        cpa16(sb + QL_OFF + r * KPAD + c * 16, qlg + (size_t)(qbase + r) * DH + c * 8);
    }
    cpa_commit();

    float oacc[16][4];
#pragma unroll
    for (int i = 0; i < 16; i++)
#pragma unroll
        for (int j = 0; j < 4; j++) oacc[i][j] = 0.f;
    float rs0 = 0.f, rs1 = 0.f, m0 = MINIT, m1 = MINIT;

    for (int it = 0; it < (NTOK / 2) / 64; it++) {
        const int t0 = tstart + it * 64;
#pragma unroll
        for (int i = 0; i < 8; i++) {
            const int idx = tid + i * 128;
            const int r = idx >> 4, c = idx & 15;
            cpa16(sb + KH_OFF + r * KPAD + c * 16, khg + (size_t)(t0 + r) * DH + c * 8);
            cpa16(sb + KL_OFF + r * KPAD + c * 16, klg + (size_t)(t0 + r) * DH + c * 8);
        }
#pragma unroll
        for (int i = 0; i < 8; i++) {
            const int idx = tid + i * 128;
            const int r = idx >> 3, c = idx & 7;
            cpa16(sb + VH_OFF + r * VPAD + c * 16, vthg + (size_t)r * NTOK + t0 + c * 8);
            cpa16(sb + VL_OFF + r * VPAD + c * 16, vtlg + (size_t)r * NTOK + t0 + c * 8);
        }
        cpa_commit();
        cpa_wait0();
        __syncthreads();

        // prefetch adjacency (consumed after S-MMA; latency hidden under MMAs)
        int2 av0[8], av1[8];
#pragma unroll
        for (int nb = 0; nb < 8; nb++) {
            const int col = t0 + nb * 8 + cq;
            av0[nb] = *(const int2*)(adj + (size_t)r0g * NTOK + col);
            av1[nb] = *(const int2*)(adj + (size_t)r1g * NTOK + col);
        }

        // ---- S = Q K^T (3-term bf16 split) ----
        float sacc[8][4];
#pragma unroll
        for (int i = 0; i < 8; i++)
#pragma unroll
            for (int j = 0; j < 4; j++) sacc[i][j] = 0.f;

#pragma unroll
        for (int kc = 0; kc < 8; kc++) {
            uint32_t qh[4], ql[4];
            ldm4(qoff + kc * 32, qh);
            ldm4(qoff + (QL_OFF - QH_OFF) + kc * 32, ql);
#pragma unroll
            for (int nb2 = 0; nb2 < 4; nb2++) {
                uint32_t kh[4], kl[4];
                ldm4(koff + nb2 * 16 * KPAD + kc * 32, kh);
                ldm4(koff + (KL_OFF - KH_OFF) + nb2 * 16 * KPAD + kc * 32, kl);
                mma_bf16(sacc[2 * nb2],     qh[0], qh[1], qh[2], qh[3], kh[0], kh[2]);
                mma_bf16(sacc[2 * nb2 + 1], qh[0], qh[1], qh[2], qh[3], kh[1], kh[3]);
                mma_bf16(sacc[2 * nb2],     qh[0], qh[1], qh[2], qh[3], kl[0], kl[2]);
                mma_bf16(sacc[2 * nb2 + 1], qh[0], qh[1], qh[2], qh[3], kl[1], kl[3]);
                mma_bf16(sacc[2 * nb2],     ql[0], ql[1], ql[2], ql[3], kh[0], kh[2]);
                mma_bf16(sacc[2 * nb2 + 1], ql[0], ql[1], ql[2], ql[3], kh[1], kh[3]);
            }
        }

        // ---- mask scores FIRST (so running max is over valid entries only) ----
#pragma unroll
        for (int nb = 0; nb < 8; nb++) {
            if (av0[nb].x <= 0) sacc[nb][0] = MNEG;
            if (av0[nb].y <= 0) sacc[nb][1] = MNEG;
            if (av1[nb].x <= 0) sacc[nb][2] = MNEG;
            if (av1[nb].y <= 0) sacc[nb][3] = MNEG;
        }

        // ---- online max + rare rescale ----
        float tm0 = MNEG, tm1 = MNEG;
#pragma unroll
        for (int nb = 0; nb < 8; nb++) {
            tm0 = fmaxf(tm0, fmaxf(sacc[nb][0], sacc[nb][1]));
            tm1 = fmaxf(tm1, fmaxf(sacc[nb][2], sacc[nb][3]));
        }
        tm0 = fmaxf(tm0, __shfl_xor_sync(0xffffffff, tm0, 1));
        tm0 = fmaxf(tm0, __shfl_xor_sync(0xffffffff, tm0, 2));
        tm1 = fmaxf(tm1, __shfl_xor_sync(0xffffffff, tm1, 1));
        tm1 = fmaxf(tm1, __shfl_xor_sync(0xffffffff, tm1, 2));
        if (tm0 > m0) {
            const float f = __expf(m0 - tm0);
            rs0 *= f;
#pragma unroll
            for (int db = 0; db < 16; db++) { oacc[db][0] *= f; oacc[db][1] *= f; }
            m0 = tm0;
        }
        if (tm1 > m1) {
            const float f = __expf(m1 - tm1);
            rs1 *= f;
#pragma unroll
            for (int db = 0; db < 16; db++) { oacc[db][2] *= f; oacc[db][3] *= f; }
            m1 = tm1;
        }

        // ---- exp -> fp16 P (hi + residual lo); masked -> exp(-huge) = 0 ----
        uint32_t ph[8][2], pl[8][2];
#pragma unroll
        for (int nb = 0; nb < 8; nb++) {
            float p00 = __expf(sacc[nb][0] - m0);
            float p01 = __expf(sacc[nb][1] - m0);
            float p10 = __expf(sacc[nb][2] - m1);
            float p11 = __expf(sacc[nb][3] - m1);
            rs0 += p00 + p01;
            rs1 += p10 + p11;
            __half2 h0 = __floats2half2_rn(p00, p01);
            __half2 h1 = __floats2half2_rn(p10, p11);
            ph[nb][0] = *(uint32_t*)&h0;
            ph[nb][1] = *(uint32_t*)&h1;
            float2 f0 = __half22float2(h0), f1 = __half22float2(h1);
            __half2 l0 = __floats2half2_rn(p00 - f0.x, p01 - f0.y);
            __half2 l1 = __floats2half2_rn(p10 - f1.x, p11 - f1.y);
            pl[nb][0] = *(uint32_t*)&l0;
            pl[nb][1] = *(uint32_t*)&l1;
        }

        // ---- O += Ph(Vh+Vl) + Pl Vh  (fp16 in, fp32 acc) ----
#pragma unroll
        for (int kc2 = 0; kc2 < 4; kc2++) {
            const uint32_t a0 = ph[2 * kc2][0], a1 = ph[2 * kc2][1];
            const uint32_t a2 = ph[2 * kc2 + 1][0], a3 = ph[2 * kc2 + 1][1];
            const uint32_t b0 = pl[2 * kc2][0], b1 = pl[2 * kc2][1];
            const uint32_t b2 = pl[2 * kc2 + 1][0], b3 = pl[2 * kc2 + 1][1];
#pragma unroll
            for (int db2 = 0; db2 < 8; db2++) {
                uint32_t vh[4], vl[4];
                ldm4(voff + db2 * 16 * VPAD + kc2 * 32, vh);
                ldm4(voff + (VL_OFF - VH_OFF) + db2 * 16 * VPAD + kc2 * 32, vl);
                mma_f16(oacc[2 * db2],     a0, a1, a2, a3, vh[0], vh[2]);
                mma_f16(oacc[2 * db2 + 1], a0, a1, a2, a3, vh[1], vh[3]);
                mma_f16(oacc[2 * db2],     a0, a1, a2, a3, vl[0], vl[2]);
                mma_f16(oacc[2 * db2 + 1], a0, a1, a2, a3, vl[1], vl[3]);
                mma_f16(oacc[2 * db2],     b0, b1, b2, b3, vh[0], vh[2]);
                mma_f16(oacc[2 * db2 + 1], b0, b1, b2, b3, vh[1], vh[3]);
            }
        }
        __syncthreads();
    }

    // ---- epilogue ----
    rs0 += __shfl_xor_sync(0xffffffff, rs0, 1);
    rs0 += __shfl_xor_sync(0xffffffff, rs0, 2);
    rs1 += __shfl_xor_sync(0xffffffff, rs1, 1);
    rs1 += __shfl_xor_sync(0xffffffff, rs1, 2);
    if ((lid & 3) == 0) {
        lp[(size_t)split * 2 * NTOK + r0g] = rs0;
        lp[(size_t)split * 2 * NTOK + NTOK + r0g] = m0;
        lp[(size_t)split * 2 * NTOK + r1g] = rs1;
        lp[(size_t)split * 2 * NTOK + NTOK + r1g] = m1;
    }
    float* mp0 = mp + ((size_t)split * NTOK + r0g) * DH;
    float* mp1 = mp + ((size_t)split * NTOK + r1g) * DH;
#pragma unroll
    for (int db = 0; db < 16; db++) {
        const int c = db * 8 + cq;
        *(float2*)(mp0 + c) = make_float2(oacc[db][0], oacc[db][1]);
        *(float2*)(mp1 + c) = make_float2(oacc[db][2], oacc[db][3]);
    }
}

// ---------------- combine splits (log-sum-exp merge) ----------------
__global__ void __launch_bounds__(256) combine_kernel(
    const float* __restrict__ mp, const float* __restrict__ lp, float* __restrict__ out)
{
    const int idx = blockIdx.x * 256 + threadIdx.x;
    const int row = idx >> 7;
    const float l0 = lp[row], mm0 = lp[NTOK + row];
    const float l1 = lp[2 * NTOK + row], mm1 = lp[3 * NTOK + row];
    const float M = fmaxf(mm0, mm1);
    const float e0 = __expf(mm0 - M), e1 = __expf(mm1 - M);
    out[idx] = (mp[idx] * e0 + mp[NTOK * DH + idx] * e1) / (l0 * e0 + l1 * e1);
}

// ---------------- fp32 GEMM (QKV + MLP) ----------------
__global__ void __launch_bounds__(256) gemm2_kernel(
    const float* __restrict__ A, const float* __restrict__ W,
    const float* __restrict__ bias, float* __restrict__ C, int relu)
{
    extern __shared__ float smf[];
    float* As = smf;
    float* Ws = smf + 64 * 128;
    const int tid = threadIdx.x;
    const int tx = tid & 15, ty = tid >> 4;
    const int r0 = blockIdx.x * 64;

    for (int idx = tid; idx < 64 * 32; idx += 256) {
        int row = idx >> 5, f4 = idx & 31;
        ((float4*)(As + row * 128))[f4] = ((const float4*)(A + (size_t)(r0 + row) * 128))[f4];
    }
    for (int idx = tid; idx < 128 * 32; idx += 256) {
        int row = idx >> 5, f4 = idx & 31;
        ((float4*)(Ws + row * 128))[f4] = ((const float4*)(W + row * 128))[f4];
    }
    __syncthreads();

    float acc[4][8];
#pragma unroll
    for (int i = 0; i < 4; i++)
#pragma unroll
        for (int j = 0; j < 8; j++) acc[i][j] = 0.f;

#pragma unroll 4
    for (int kk = 0; kk < 128; kk++) {
        float a0 = As[(ty * 4 + 0) * 128 + kk];
        float a1 = As[(ty * 4 + 1) * 128 + kk];
        float a2 = As[(ty * 4 + 2) * 128 + kk];
        float a3 = As[(ty * 4 + 3) * 128 + kk];
        float4 w0 = ((float4*)(Ws + kk * 128))[tx * 2];
        float4 w1 = ((float4*)(Ws + kk * 128))[tx * 2 + 1];
        acc[0][0] += a0 * w0.x; acc[0][1] += a0 * w0.y; acc[0][2] += a0 * w0.z; acc[0][3] += a0 * w0.w;
        acc[0][4] += a0 * w1.x; acc[0][5] += a0 * w1.y; acc[0][6] += a0 * w1.z; acc[0][7] += a0 * w1.w;
        acc[1][0] += a1 * w0.x; acc[1][1] += a1 * w0.y; acc[1][2] += a1 * w0.z; acc[1][3] += a1 * w0.w;
        acc[1][4] += a1 * w1.x; acc[1][5] += a1 * w1.y; acc[1][6] += a1 * w1.z; acc[1][7] += a1 * w1.w;
        acc[2][0] += a2 * w0.x; acc[2][1] += a2 * w0.y; acc[2][2] += a2 * w0.z; acc[2][3] += a2 * w0.w;
        acc[2][4] += a2 * w1.x; acc[2][5] += a2 * w1.y; acc[2][6] += a2 * w1.z; acc[2][7] += a2 * w1.w;
        acc[3][0] += a3 * w0.x; acc[3][1] += a3 * w0.y; acc[3][2] += a3 * w0.z; acc[3][3] += a3 * w0.w;
        acc[3][4] += a3 * w1.x; acc[3][5] += a3 * w1.y; acc[3][6] += a3 * w1.z; acc[3][7] += a3 * w1.w;
    }

#pragma unroll
    for (int i = 0; i < 4; i++) {
        float* crow = C + (size_t)(r0 + ty * 4 + i) * 128 + tx * 8;
#pragma unroll
        for (int j = 0; j < 8; j++) {
            float v = acc[i][j] + (bias ? bias[tx * 8 + j] : 0.f);
            if (relu) v = fmaxf(v, 0.f);
            crow[j] = v;
        }
    }
}

// ---------------- launch ----------------
extern "C" void kernel_launch(void* const* d_in, const int* in_sizes, int n_in,
                              void* d_out, int out_size)
{
    const float* H   = (const float*)d_in[0];
    const int*   adj = (const int*)d_in[1];
    const float* Wq  = (const float*)d_in[2];
    const float* Wk  = (const float*)d_in[3];
    const float* Wv  = (const float*)d_in[4];
    const float* W1  = (const float*)d_in[5];
    const float* b1  = (const float*)d_in[6];
    const float* W2  = (const float*)d_in[7];
    const float* b2  = (const float*)d_in[8];
    float* out = (float*)d_out;

    float *q, *k, *v, *mpd, *lpd, *m, *h;
    __nv_bfloat16 *qh, *ql, *kh, *kl;
    __half *vth, *vtl;
    cudaGetSymbolAddress((void**)&q,   g_q);
    cudaGetSymbolAddress((void**)&k,   g_k);
    cudaGetSymbolAddress((void**)&v,   g_v);
    cudaGetSymbolAddress((void**)&qh,  g_qh);
    cudaGetSymbolAddress((void**)&ql,  g_ql);
    cudaGetSymbolAddress((void**)&kh,  g_kh);
    cudaGetSymbolAddress((void**)&kl,  g_kl);
    cudaGetSymbolAddress((void**)&vth, g_vth);
    cudaGetSymbolAddress((void**)&vtl, g_vtl);
    cudaGetSymbolAddress((void**)&mpd, g_mp);
    cudaGetSymbolAddress((void**)&lpd, g_lp);
    cudaGetSymbolAddress((void**)&m,   g_m);
    cudaGetSymbolAddress((void**)&h,   g_h);

    cudaFuncSetAttribute(attn_kernel, cudaFuncAttributeMaxDynamicSharedMemorySize, ATT_SMEM);
    cudaFuncSetAttribute(gemm2_kernel, cudaFuncAttributeMaxDynamicSharedMemorySize, 96 * 1024);

    const int gsm = 96 * 1024;
    gemm2_kernel<<<NTOK / 64, 256, gsm>>>(H, Wq, nullptr, q, 0);
    gemm2_kernel<<<NTOK / 64, 256, gsm>>>(H, Wk, nullptr, k, 0);
    gemm2_kernel<<<NTOK / 64, 256, gsm>>>(H, Wv, nullptr, v, 0);

    qkconv_kernel<<<dim3(NTOK * DH / 4 / 256, 2), 256>>>(q, k, qh, ql, kh, kl);
    vtconv_kernel<<<dim3(NTOK / 32, DH / 32), 256>>>(v, vth, vtl);

    attn_kernel<<<dim3(NTOK / 64, 2), 128, ATT_SMEM>>>(qh, ql, kh, kl, vth, vtl,
                                                       adj, mpd, lpd);

    combine_kernel<<<NTOK * DH / 256, 256>>>(mpd, lpd, m);

    gemm2_kernel<<<NTOK / 64, 256, gsm>>>(m, W1, b1, h, 1);
    gemm2_kernel<<<NTOK / 64, 256, gsm>>>(h, W2, b2, out, 1);
}

// round 7
// speedup vs baseline: 4.2709x; 1.0623x over previous
#include <cuda_runtime.h>
#include <cuda_bf16.h>
#include <cuda_fp16.h>
#include <cstdint>

#define NTOK 8192
#define DH   128

// ---------------- scratch ----------------
__device__ float g_q[NTOK * DH];
__device__ float g_k[NTOK * DH];
__device__ float g_v[NTOK * DH];
__device__ __nv_bfloat16 g_qh[NTOK * DH];
__device__ __nv_bfloat16 g_ql[NTOK * DH];
__device__ __nv_bfloat16 g_kh[NTOK * DH];
__device__ __nv_bfloat16 g_kl[NTOK * DH];
__device__ __half g_vth[DH * NTOK];
__device__ __half g_vtl[DH * NTOK];
__device__ float g_mp[2 * NTOK * DH];
__device__ float g_lp[4 * NTOK];       // [split][rs | m][row]
__device__ float g_m[NTOK * DH];
__device__ float g_h[NTOK * DH];

// ---------------- helpers ----------------
__device__ __forceinline__ uint32_t smem_u32(const void* p) {
    uint32_t a;
    asm("{ .reg .u64 t; cvta.to.shared.u64 t, %1; cvt.u32.u64 %0, t; }" : "=r"(a) : "l"(p));
    return a;
}
__device__ __forceinline__ void cpa16(uint32_t dst, const void* src) {
    asm volatile("cp.async.cg.shared.global [%0], [%1], 16;" :: "r"(dst), "l"(src));
}
__device__ __forceinline__ void cpa_commit() {
    asm volatile("cp.async.commit_group;" ::: "memory");
}
__device__ __forceinline__ void cpa_wait0() {
    asm volatile("cp.async.wait_group 0;" ::: "memory");
}
__device__ __forceinline__ void ldm4(uint32_t addr, uint32_t r[4]) {
    asm volatile("ldmatrix.sync.aligned.m8n8.x4.shared.b16 {%0,%1,%2,%3}, [%4];"
                 : "=r"(r[0]), "=r"(r[1]), "=r"(r[2]), "=r"(r[3]) : "r"(addr));
}
__device__ __forceinline__ void mma_bf16(float c[4], uint32_t a0, uint32_t a1,
                                         uint32_t a2, uint32_t a3,
                                         uint32_t b0, uint32_t b1) {
    asm volatile("mma.sync.aligned.m16n8k16.row.col.f32.bf16.bf16.f32 "
                 "{%0,%1,%2,%3}, {%4,%5,%6,%7}, {%8,%9}, {%0,%1,%2,%3};"
                 : "+f"(c[0]), "+f"(c[1]), "+f"(c[2]), "+f"(c[3])
                 : "r"(a0), "r"(a1), "r"(a2), "r"(a3), "r"(b0), "r"(b1));
}
__device__ __forceinline__ void mma_f16(float c[4], uint32_t a0, uint32_t a1,
                                        uint32_t a2, uint32_t a3,
                                        uint32_t b0, uint32_t b1) {
    asm volatile("mma.sync.aligned.m16n8k16.row.col.f32.f16.f16.f32 "
                 "{%0,%1,%2,%3}, {%4,%5,%6,%7}, {%8,%9}, {%0,%1,%2,%3};"
                 : "+f"(c[0]), "+f"(c[1]), "+f"(c[2]), "+f"(c[3])
                 : "r"(a0), "r"(a1), "r"(a2), "r"(a3), "r"(b0), "r"(b1));
}
__device__ __forceinline__ uint32_t pkbf(float a, float b) {
    __nv_bfloat162 t = __floats2bfloat162_rn(a, b);
    return *reinterpret_cast<uint32_t*>(&t);
}

// ---------------- pre-convert kernels ----------------
__global__ void __launch_bounds__(256) qkconv_kernel(
    const float* __restrict__ q, const float* __restrict__ k,
    __nv_bfloat16* __restrict__ qh, __nv_bfloat16* __restrict__ ql,
    __nv_bfloat16* __restrict__ kh, __nv_bfloat16* __restrict__ kl)
{
    const int idx = blockIdx.x * 256 + threadIdx.x;       // float4 index
    const float* src = blockIdx.y ? k : q;
    __nv_bfloat16* dh = blockIdx.y ? kh : qh;
    __nv_bfloat16* dl = blockIdx.y ? kl : ql;
    float4 v = ((const float4*)src)[idx];
    __nv_bfloat16 h0 = __float2bfloat16(v.x), h1 = __float2bfloat16(v.y);
    __nv_bfloat16 h2 = __float2bfloat16(v.z), h3 = __float2bfloat16(v.w);
    __nv_bfloat162 hv0 = __halves2bfloat162(h0, h1), hv1 = __halves2bfloat162(h2, h3);
    ((uint2*)dh)[idx] = make_uint2(*(uint32_t*)&hv0, *(uint32_t*)&hv1);
    ((uint2*)dl)[idx] = make_uint2(pkbf(v.x - __bfloat162float(h0), v.y - __bfloat162float(h1)),
                                   pkbf(v.z - __bfloat162float(h2), v.w - __bfloat162float(h3)));
}

__global__ void __launch_bounds__(256) vtconv_kernel(
    const float* __restrict__ v, __half* __restrict__ vth, __half* __restrict__ vtl)
{
    __shared__ float ts[32][33];
    const int tb0 = blockIdx.x * 32, db0 = blockIdx.y * 32;
    const int x = threadIdx.x & 31, y = threadIdx.x >> 5;
#pragma unroll
    for (int i = 0; i < 32; i += 8)
        ts[y + i][x] = v[(size_t)(tb0 + y + i) * DH + db0 + x];
    __syncthreads();
#pragma unroll
    for (int i = 0; i < 32; i += 8) {
        float val = ts[x][y + i];
        __half h = __float2half_rn(val);
        __half l = __float2half_rn(val - __half2float(h));
        vth[(size_t)(db0 + y + i) * NTOK + tb0 + x] = h;
        vtl[(size_t)(db0 + y + i) * NTOK + tb0 + x] = l;
    }
}

// ---------------- fused attention ----------------
#define QH_OFF 0
#define QL_OFF 17408
#define KH_OFF 34816
#define KL_OFF 52224
#define VH_OFF 69632
#define VL_OFF 88064
#define ATT_SMEM 106496
#define KPAD 272
#define VPAD 144
#define MNEG  -1e30f    // masked-score sentinel
#define MINIT -1e29f    // running-max init (> MNEG so all-masked tiles yield p=0)

__global__ void __launch_bounds__(128, 2) attn_kernel(
    const __nv_bfloat16* __restrict__ qhg, const __nv_bfloat16* __restrict__ qlg,
    const __nv_bfloat16* __restrict__ khg, const __nv_bfloat16* __restrict__ klg,
    const __half* __restrict__ vthg, const __half* __restrict__ vtlg,
    const int* __restrict__ adj, float* __restrict__ mp, float* __restrict__ lp)
{
    extern __shared__ char smc[];
    const uint32_t sb = smem_u32(smc);
    const int tid = threadIdx.x;
    const int wid = tid >> 5, lid = tid & 31;
    const int wrow = wid * 16;
    const int qbase = blockIdx.x * 64;
    const int split = blockIdx.y;
    const int tstart = split * (NTOK / 2);

    const int lrow = lid & 15, lcol = (lid >> 4) * 8;
    const uint32_t qoff = sb + QH_OFF + (wrow + lrow) * KPAD + lcol * 2;
    const uint32_t koff = sb + KH_OFF + lrow * KPAD + lcol * 2;
    const uint32_t voff = sb + VH_OFF + lrow * VPAD + lcol * 2;

    const int fr0 = wrow + (lid >> 2);
    const int r0g = qbase + fr0;
    const int r1g = r0g + 8;
    const int cq = 2 * (lid & 3);

    // Q tile (its own commit group; first tile's wait covers it)
#pragma unroll
    for (int i = 0; i < 8; i++) {
        const int idx = tid + i * 128;
        const int r = idx >> 4, c = idx & 15;
        cpa16(sb + QH_OFF + r * KPAD + c * 16, qhg + (size_t)(qbase + r) * DH + c * 8);
        cpa16(sb + QL_OFF + r * KPAD + c * 16, qlg + (size_t)(qbase + r) * DH + c * 8);
    }
    cpa_commit();

    float oacc[16][4];
#pragma unroll
    for (int i = 0; i < 16; i++)
#pragma unroll
        for (int j = 0; j < 4; j++) oacc[i][j] = 0.f;
    float rs0 = 0.f, rs1 = 0.f, m0 = MINIT, m1 = MINIT;

    for (int it = 0; it < (NTOK / 2) / 64; it++) {
        const int t0 = tstart + it * 64;
#pragma unroll
        for (int i = 0; i < 8; i++) {
            const int idx = tid + i * 128;
            const int r = idx >> 4, c = idx & 15;
            cpa16(sb + KH_OFF + r * KPAD + c * 16, khg + (size_t)(t0 + r) * DH + c * 8);
            cpa16(sb + KL_OFF + r * KPAD + c * 16, klg + (size_t)(t0 + r) * DH + c * 8);
        }
#pragma unroll
        for (int i = 0; i < 8; i++) {
            const int idx = tid + i * 128;
            const int r = idx >> 3, c = idx & 7;
            cpa16(sb + VH_OFF + r * VPAD + c * 16, vthg + (size_t)r * NTOK + t0 + c * 8);
            cpa16(sb + VL_OFF + r * VPAD + c * 16, vtlg + (size_t)r * NTOK + t0 + c * 8);
        }
        cpa_commit();
        cpa_wait0();
        __syncthreads();

        // prefetch adjacency (consumed after S-MMA; latency hidden under MMAs)
        int2 av0[8], av1[8];
#pragma unroll
        for (int nb = 0; nb < 8; nb++) {
            const int col = t0 + nb * 8 + cq;
            av0[nb] = *(const int2*)(adj + (size_t)r0g * NTOK + col);
            av1[nb] = *(const int2*)(adj + (size_t)r1g * NTOK + col);
        }

        // ---- S = Q K^T (3-term bf16 split) ----
        float sacc[8][4];
#pragma unroll
        for (int i = 0; i < 8; i++)
#pragma unroll
            for (int j = 0; j < 4; j++) sacc[i][j] = 0.f;

#pragma unroll
        for (int kc = 0; kc < 8; kc++) {
            uint32_t qh[4], ql[4];
            ldm4(qoff + kc * 32, qh);
            ldm4(qoff + (QL_OFF - QH_OFF) + kc * 32, ql);
#pragma unroll
            for (int nb2 = 0; nb2 < 4; nb2++) {
                uint32_t kh[4], kl[4];
                ldm4(koff + nb2 * 16 * KPAD + kc * 32, kh);
                ldm4(koff + (KL_OFF - KH_OFF) + nb2 * 16 * KPAD + kc * 32, kl);
                mma_bf16(sacc[2 * nb2],     qh[0], qh[1], qh[2], qh[3], kh[0], kh[2]);
                mma_bf16(sacc[2 * nb2 + 1], qh[0], qh[1], qh[2], qh[3], kh[1], kh[3]);
                mma_bf16(sacc[2 * nb2],     qh[0], qh[1], qh[2], qh[3], kl[0], kl[2]);
                mma_bf16(sacc[2 * nb2 + 1], qh[0], qh[1], qh[2], qh[3], kl[1], kl[3]);
                mma_bf16(sacc[2 * nb2],     ql[0], ql[1], ql[2], ql[3], kh[0], kh[2]);
                mma_bf16(sacc[2 * nb2 + 1], ql[0], ql[1], ql[2], ql[3], kh[1], kh[3]);
            }
        }

        // ---- mask scores FIRST (so running max is over valid entries only) ----
#pragma unroll
        for (int nb = 0; nb < 8; nb++) {
            if (av0[nb].x <= 0) sacc[nb][0] = MNEG;
            if (av0[nb].y <= 0) sacc[nb][1] = MNEG;
            if (av1[nb].x <= 0) sacc[nb][2] = MNEG;
            if (av1[nb].y <= 0) sacc[nb][3] = MNEG;
        }

        // ---- online max + rare rescale ----
        float tm0 = MNEG, tm1 = MNEG;
#pragma unroll
        for (int nb = 0; nb < 8; nb++) {
            tm0 = fmaxf(tm0, fmaxf(sacc[nb][0], sacc[nb][1]));
            tm1 = fmaxf(tm1, fmaxf(sacc[nb][2], sacc[nb][3]));
        }
        tm0 = fmaxf(tm0, __shfl_xor_sync(0xffffffff, tm0, 1));
        tm0 = fmaxf(tm0, __shfl_xor_sync(0xffffffff, tm0, 2));
        tm1 = fmaxf(tm1, __shfl_xor_sync(0xffffffff, tm1, 1));
        tm1 = fmaxf(tm1, __shfl_xor_sync(0xffffffff, tm1, 2));
        if (tm0 > m0) {
            const float f = __expf(m0 - tm0);
            rs0 *= f;
#pragma unroll
            for (int db = 0; db < 16; db++) { oacc[db][0] *= f; oacc[db][1] *= f; }
            m0 = tm0;
        }
        if (tm1 > m1) {
            const float f = __expf(m1 - tm1);
            rs1 *= f;
#pragma unroll
            for (int db = 0; db < 16; db++) { oacc[db][2] *= f; oacc[db][3] *= f; }
            m1 = tm1;
        }

        // ---- exp -> fp16 P; row-sum accumulates the ROUNDED p-hat so the
        //      softmax normalization is self-consistent (error cancels) ----
        uint32_t ph[8][2];
#pragma unroll
        for (int nb = 0; nb < 8; nb++) {
            float p00 = __expf(sacc[nb][0] - m0);
            float p01 = __expf(sacc[nb][1] - m0);
            float p10 = __expf(sacc[nb][2] - m1);
            float p11 = __expf(sacc[nb][3] - m1);
            __half2 h0 = __floats2half2_rn(p00, p01);
            __half2 h1 = __floats2half2_rn(p10, p11);
            ph[nb][0] = *(uint32_t*)&h0;
            ph[nb][1] = *(uint32_t*)&h1;
            float2 f0 = __half22float2(h0), f1 = __half22float2(h1);
            rs0 += f0.x + f0.y;
            rs1 += f1.x + f1.y;
        }

        // ---- O += Ph (Vh + Vl)  (2-term PV, fp16 in, fp32 acc) ----
#pragma unroll
        for (int kc2 = 0; kc2 < 4; kc2++) {
            const uint32_t a0 = ph[2 * kc2][0], a1 = ph[2 * kc2][1];
            const uint32_t a2 = ph[2 * kc2 + 1][0], a3 = ph[2 * kc2 + 1][1];
#pragma unroll
            for (int db2 = 0; db2 < 8; db2++) {
                uint32_t vh[4], vl[4];
                ldm4(voff + db2 * 16 * VPAD + kc2 * 32, vh);
                ldm4(voff + (VL_OFF - VH_OFF) + db2 * 16 * VPAD + kc2 * 32, vl);
                mma_f16(oacc[2 * db2],     a0, a1, a2, a3, vh[0], vh[2]);
                mma_f16(oacc[2 * db2 + 1], a0, a1, a2, a3, vh[1], vh[3]);
                mma_f16(oacc[2 * db2],     a0, a1, a2, a3, vl[0], vl[2]);
                mma_f16(oacc[2 * db2 + 1], a0, a1, a2, a3, vl[1], vl[3]);
            }
        }
        __syncthreads();
    }

    // ---- epilogue ----
    rs0 += __shfl_xor_sync(0xffffffff, rs0, 1);
    rs0 += __shfl_xor_sync(0xffffffff, rs0, 2);
    rs1 += __shfl_xor_sync(0xffffffff, rs1, 1);
    rs1 += __shfl_xor_sync(0xffffffff, rs1, 2);
    if ((lid & 3) == 0) {
        lp[(size_t)split * 2 * NTOK + r0g] = rs0;
        lp[(size_t)split * 2 * NTOK + NTOK + r0g] = m0;
        lp[(size_t)split * 2 * NTOK + r1g] = rs1;
        lp[(size_t)split * 2 * NTOK + NTOK + r1g] = m1;
    }
    float* mp0 = mp + ((size_t)split * NTOK + r0g) * DH;
    float* mp1 = mp + ((size_t)split * NTOK + r1g) * DH;
#pragma unroll
    for (int db = 0; db < 16; db++) {
        const int c = db * 8 + cq;
        *(float2*)(mp0 + c) = make_float2(oacc[db][0], oacc[db][1]);
        *(float2*)(mp1 + c) = make_float2(oacc[db][2], oacc[db][3]);
    }
}

// ---------------- combine splits (log-sum-exp merge) ----------------
__global__ void __launch_bounds__(256) combine_kernel(
    const float* __restrict__ mp, const float* __restrict__ lp, float* __restrict__ out)
{
    const int idx = blockIdx.x * 256 + threadIdx.x;
    const int row = idx >> 7;
    const float l0 = lp[row], mm0 = lp[NTOK + row];
    const float l1 = lp[2 * NTOK + row], mm1 = lp[3 * NTOK + row];
    const float M = fmaxf(mm0, mm1);
    const float e0 = __expf(mm0 - M), e1 = __expf(mm1 - M);
    out[idx] = (mp[idx] * e0 + mp[NTOK * DH + idx] * e1) / (l0 * e0 + l1 * e1);
}

// ---------------- fp32 GEMM (QKV + MLP) ----------------
__global__ void __launch_bounds__(256) gemm2_kernel(
    const float* __restrict__ A, const float* __restrict__ W,
    const float* __restrict__ bias, float* __restrict__ C, int relu)
{
    extern __shared__ float smf[];
    float* As = smf;
    float* Ws = smf + 64 * 128;
    const int tid = threadIdx.x;
    const int tx = tid & 15, ty = tid >> 4;
    const int r0 = blockIdx.x * 64;

    for (int idx = tid; idx < 64 * 32; idx += 256) {
        int row = idx >> 5, f4 = idx & 31;
        ((float4*)(As + row * 128))[f4] = ((const float4*)(A + (size_t)(r0 + row) * 128))[f4];
    }
    for (int idx = tid; idx < 128 * 32; idx += 256) {
        int row = idx >> 5, f4 = idx & 31;
        ((float4*)(Ws + row * 128))[f4] = ((const float4*)(W + row * 128))[f4];
    }
    __syncthreads();

    float acc[4][8];
#pragma unroll
    for (int i = 0; i < 4; i++)
#pragma unroll
        for (int j = 0; j < 8; j++) acc[i][j] = 0.f;

#pragma unroll 4
    for (int kk = 0; kk < 128; kk++) {
        float a0 = As[(ty * 4 + 0) * 128 + kk];
        float a1 = As[(ty * 4 + 1) * 128 + kk];
        float a2 = As[(ty * 4 + 2) * 128 + kk];
        float a3 = As[(ty * 4 + 3) * 128 + kk];
        float4 w0 = ((float4*)(Ws + kk * 128))[tx * 2];
        float4 w1 = ((float4*)(Ws + kk * 128))[tx * 2 + 1];
        acc[0][0] += a0 * w0.x; acc[0][1] += a0 * w0.y; acc[0][2] += a0 * w0.z; acc[0][3] += a0 * w0.w;
        acc[0][4] += a0 * w1.x; acc[0][5] += a0 * w1.y; acc[0][6] += a0 * w1.z; acc[0][7] += a0 * w1.w;
        acc[1][0] += a1 * w0.x; acc[1][1] += a1 * w0.y; acc[1][2] += a1 * w0.z; acc[1][3] += a1 * w0.w;
        acc[1][4] += a1 * w1.x; acc[1][5] += a1 * w1.y; acc[1][6] += a1 * w1.z; acc[1][7] += a1 * w1.w;
        acc[2][0] += a2 * w0.x; acc[2][1] += a2 * w0.y; acc[2][2] += a2 * w0.z; acc[2][3] += a2 * w0.w;
        acc[2][4] += a2 * w1.x; acc[2][5] += a2 * w1.y; acc[2][6] += a2 * w1.z; acc[2][7] += a2 * w1.w;
        acc[3][0] += a3 * w0.x; acc[3][1] += a3 * w0.y; acc[3][2] += a3 * w0.z; acc[3][3] += a3 * w0.w;
        acc[3][4] += a3 * w1.x; acc[3][5] += a3 * w1.y; acc[3][6] += a3 * w1.z; acc[3][7] += a3 * w1.w;
    }

#pragma unroll
    for (int i = 0; i < 4; i++) {
        float* crow = C + (size_t)(r0 + ty * 4 + i) * 128 + tx * 8;
#pragma unroll
        for (int j = 0; j < 8; j++) {
            float v = acc[i][j] + (bias ? bias[tx * 8 + j] : 0.f);
            if (relu) v = fmaxf(v, 0.f);
            crow[j] = v;
        }
    }
}

// ---------------- launch ----------------
extern "C" void kernel_launch(void* const* d_in, const int* in_sizes, int n_in,
                              void* d_out, int out_size)
{
    const float* H   = (const float*)d_in[0];
    const int*   adj = (const int*)d_in[1];
    const float* Wq  = (const float*)d_in[2];
    const float* Wk  = (const float*)d_in[3];
    const float* Wv  = (const float*)d_in[4];
    const float* W1  = (const float*)d_in[5];
    const float* b1  = (const float*)d_in[6];
    const float* W2  = (const float*)d_in[7];
    const float* b2  = (const float*)d_in[8];
    float* out = (float*)d_out;

    float *q, *k, *v, *mpd, *lpd, *m, *h;
    __nv_bfloat16 *qh, *ql, *kh, *kl;
    __half *vth, *vtl;
    cudaGetSymbolAddress((void**)&q,   g_q);
    cudaGetSymbolAddress((void**)&k,   g_k);
    cudaGetSymbolAddress((void**)&v,   g_v);
    cudaGetSymbolAddress((void**)&qh,  g_qh);
    cudaGetSymbolAddress((void**)&ql,  g_ql);
    cudaGetSymbolAddress((void**)&kh,  g_kh);
    cudaGetSymbolAddress((void**)&kl,  g_kl);
    cudaGetSymbolAddress((void**)&vth, g_vth);
    cudaGetSymbolAddress((void**)&vtl, g_vtl);
    cudaGetSymbolAddress((void**)&mpd, g_mp);
    cudaGetSymbolAddress((void**)&lpd, g_lp);
    cudaGetSymbolAddress((void**)&m,   g_m);
    cudaGetSymbolAddress((void**)&h,   g_h);

    cudaFuncSetAttribute(attn_kernel, cudaFuncAttributeMaxDynamicSharedMemorySize, ATT_SMEM);
    cudaFuncSetAttribute(gemm2_kernel, cudaFuncAttributeMaxDynamicSharedMemorySize, 96 * 1024);

    const int gsm = 96 * 1024;
    gemm2_kernel<<<NTOK / 64, 256, gsm>>>(H, Wq, nullptr, q, 0);
    gemm2_kernel<<<NTOK / 64, 256, gsm>>>(H, Wk, nullptr, k, 0);
    gemm2_kernel<<<NTOK / 64, 256, gsm>>>(H, Wv, nullptr, v, 0);

    qkconv_kernel<<<dim3(NTOK * DH / 4 / 256, 2), 256>>>(q, k, qh, ql, kh, kl);
    vtconv_kernel<<<dim3(NTOK / 32, DH / 32), 256>>>(v, vth, vtl);

    attn_kernel<<<dim3(NTOK / 64, 2), 128, ATT_SMEM>>>(qh, ql, kh, kl, vth, vtl,
                                                       adj, mpd, lpd);

    combine_kernel<<<NTOK * DH / 256, 256>>>(mpd, lpd, m);

    gemm2_kernel<<<NTOK / 64, 256, gsm>>>(m, W1, b1, h, 1);
    gemm2_kernel<<<NTOK / 64, 256, gsm>>>(h, W2, b2, out, 1);
}

// round 8
// speedup vs baseline: 4.8177x; 1.1280x over previous
#include <cuda_runtime.h>
#include <cuda_bf16.h>
#include <cuda_fp16.h>
#include <cstdint>

#define NTOK 8192
#define DH   128

// ---------------- scratch ----------------
__device__ float g_q[NTOK * DH];
__device__ float g_k[NTOK * DH];
__device__ float g_v[NTOK * DH];
__device__ __nv_bfloat16 g_qh[NTOK * DH];
__device__ __nv_bfloat16 g_ql[NTOK * DH];
__device__ __nv_bfloat16 g_kh[NTOK * DH];
__device__ __nv_bfloat16 g_kl[NTOK * DH];
__device__ __half g_vth[DH * NTOK];
__device__ float g_mp[2 * NTOK * DH];
__device__ float g_lp[4 * NTOK];       // [split][rs | m][row]
__device__ float g_m[NTOK * DH];
__device__ float g_h[NTOK * DH];

// ---------------- helpers ----------------
__device__ __forceinline__ uint32_t smem_u32(const void* p) {
    uint32_t a;
    asm("{ .reg .u64 t; cvta.to.shared.u64 t, %1; cvt.u32.u64 %0, t; }" : "=r"(a) : "l"(p));
    return a;
}
__device__ __forceinline__ void cpa16(uint32_t dst, const void* src) {
    asm volatile("cp.async.cg.shared.global [%0], [%1], 16;" :: "r"(dst), "l"(src));
}
__device__ __forceinline__ void cpa_commit() {
    asm volatile("cp.async.commit_group;" ::: "memory");
}
template <int N>
__device__ __forceinline__ void cpa_wait() {
    asm volatile("cp.async.wait_group %0;" :: "n"(N) : "memory");
}
__device__ __forceinline__ void ldm4(uint32_t addr, uint32_t r[4]) {
    asm volatile("ldmatrix.sync.aligned.m8n8.x4.shared.b16 {%0,%1,%2,%3}, [%4];"
                 : "=r"(r[0]), "=r"(r[1]), "=r"(r[2]), "=r"(r[3]) : "r"(addr));
}
__device__ __forceinline__ void mma_bf16(float c[4], uint32_t a0, uint32_t a1,
                                         uint32_t a2, uint32_t a3,
                                         uint32_t b0, uint32_t b1) {
    asm volatile("mma.sync.aligned.m16n8k16.row.col.f32.bf16.bf16.f32 "
                 "{%0,%1,%2,%3}, {%4,%5,%6,%7}, {%8,%9}, {%0,%1,%2,%3};"
                 : "+f"(c[0]), "+f"(c[1]), "+f"(c[2]), "+f"(c[3])
                 : "r"(a0), "r"(a1), "r"(a2), "r"(a3), "r"(b0), "r"(b1));
}
__device__ __forceinline__ void mma_f16(float c[4], uint32_t a0, uint32_t a1,
                                        uint32_t a2, uint32_t a3,
                                        uint32_t b0, uint32_t b1) {
    asm volatile("mma.sync.aligned.m16n8k16.row.col.f32.f16.f16.f32 "
                 "{%0,%1,%2,%3}, {%4,%5,%6,%7}, {%8,%9}, {%0,%1,%2,%3};"
                 : "+f"(c[0]), "+f"(c[1]), "+f"(c[2]), "+f"(c[3])
                 : "r"(a0), "r"(a1), "r"(a2), "r"(a3), "r"(b0), "r"(b1));
}
__device__ __forceinline__ uint32_t pkbf(float a, float b) {
    __nv_bfloat162 t = __floats2bfloat162_rn(a, b);
    return *reinterpret_cast<uint32_t*>(&t);
}

// ---------------- pre-convert kernels ----------------
__global__ void __launch_bounds__(256) qkconv_kernel(
    const float* __restrict__ q, const float* __restrict__ k,
    __nv_bfloat16* __restrict__ qh, __nv_bfloat16* __restrict__ ql,
    __nv_bfloat16* __restrict__ kh, __nv_bfloat16* __restrict__ kl)
{
    const int idx = blockIdx.x * 256 + threadIdx.x;       // float4 index
    const float* src = blockIdx.y ? k : q;
    __nv_bfloat16* dh = blockIdx.y ? kh : qh;
    __nv_bfloat16* dl = blockIdx.y ? kl : ql;
    float4 v = ((const float4*)src)[idx];
    __nv_bfloat16 h0 = __float2bfloat16(v.x), h1 = __float2bfloat16(v.y);
    __nv_bfloat16 h2 = __float2bfloat16(v.z), h3 = __float2bfloat16(v.w);
    __nv_bfloat162 hv0 = __halves2bfloat162(h0, h1), hv1 = __halves2bfloat162(h2, h3);
    ((uint2*)dh)[idx] = make_uint2(*(uint32_t*)&hv0, *(uint32_t*)&hv1);
    ((uint2*)dl)[idx] = make_uint2(pkbf(v.x - __bfloat162float(h0), v.y - __bfloat162float(h1)),
                                   pkbf(v.z - __bfloat162float(h2), v.w - __bfloat162float(h3)));
}

// V fp32 [t][d] -> transposed single fp16 [d][t]
__global__ void __launch_bounds__(256) vtconv_kernel(
    const float* __restrict__ v, __half* __restrict__ vth)
{
    __shared__ float ts[32][33];
    const int tb0 = blockIdx.x * 32, db0 = blockIdx.y * 32;
    const int x = threadIdx.x & 31, y = threadIdx.x >> 5;
#pragma unroll
    for (int i = 0; i < 32; i += 8)
        ts[y + i][x] = v[(size_t)(tb0 + y + i) * DH + db0 + x];
    __syncthreads();
#pragma unroll
    for (int i = 0; i < 32; i += 8)
        vth[(size_t)(db0 + y + i) * NTOK + tb0 + x] = __float2half_rn(ts[x][y + i]);
}

// ---------------- fused attention ----------------
// 128 CTAs (64 q-tiles x 2 splits), 256 threads, 128 q-rows/CTA, BN=64,
// double-buffered K/V stages, occ 1.
#define KPAD 272
#define VPAD 144
#define QH_OFF 0
#define QL_OFF 34816              // 128*272
#define STG0   69632
#define STG_SZ 53248              // KH(17408)+KL(17408)+VH(18432)
#define SK_H   0
#define SK_L   17408
#define SV_H   34816
#define ATT_SMEM (STG0 + 2 * STG_SZ)   // 176128
#define MNEG  -1e30f
#define MINIT -1e29f

__global__ void __launch_bounds__(256, 1) attn_kernel(
    const __nv_bfloat16* __restrict__ qhg, const __nv_bfloat16* __restrict__ qlg,
    const __nv_bfloat16* __restrict__ khg, const __nv_bfloat16* __restrict__ klg,
    const __half* __restrict__ vthg,
    const int* __restrict__ adj, float* __restrict__ mp, float* __restrict__ lp)
{
    extern __shared__ char smc[];
    const uint32_t sb = smem_u32(smc);
    const int tid = threadIdx.x;
    const int wid = tid >> 5, lid = tid & 31;
    const int wrow = wid * 16;
    const int qbase = blockIdx.x * 128;
    const int split = blockIdx.y;
    const int tstart = split * (NTOK / 2);
    const int ntiles = (NTOK / 2) / 64;

    const int lrow = lid & 15, lcol = (lid >> 4) * 8;
    const uint32_t qoff = sb + QH_OFF + (wrow + lrow) * KPAD + lcol * 2;
    const uint32_t kbase = sb + STG0 + lrow * KPAD + lcol * 2;   // + stage*STG_SZ (+SK_L)
    const uint32_t vbase = sb + STG0 + SV_H + lrow * VPAD + lcol * 2;

    const int fr0 = wrow + (lid >> 2);
    const int r0g = qbase + fr0;
    const int r1g = r0g + 8;
    const int cq = 2 * (lid & 3);

    // Q tile (group 0)
#pragma unroll
    for (int i = 0; i < 8; i++) {
        const int idx = tid + i * 256;
        const int r = idx >> 4, c = idx & 15;
        cpa16(sb + QH_OFF + r * KPAD + c * 16, qhg + (size_t)(qbase + r) * DH + c * 8);
        cpa16(sb + QL_OFF + r * KPAD + c * 16, qlg + (size_t)(qbase + r) * DH + c * 8);
    }
    cpa_commit();

    // stage-load helper (as a lambda-like macro over t0 and stage base)
#define LOAD_STAGE(stg, T0)                                                              \
    do {                                                                                 \
        const uint32_t sbase = sb + STG0 + (stg) * STG_SZ;                               \
        _Pragma("unroll")                                                                \
        for (int i = 0; i < 4; i++) {                                                    \
            const int idx = tid + i * 256;                                               \
            const int r = idx >> 4, c = idx & 15;                                        \
            cpa16(sbase + SK_H + r * KPAD + c * 16, khg + (size_t)((T0) + r) * DH + c * 8); \
            cpa16(sbase + SK_L + r * KPAD + c * 16, klg + (size_t)((T0) + r) * DH + c * 8); \
        }                                                                                \
        _Pragma("unroll")                                                                \
        for (int i = 0; i < 4; i++) {                                                    \
            const int idx = tid + i * 256;                                               \
            const int r = idx >> 3, c = idx & 7;                                         \
            cpa16(sbase + SV_H + r * VPAD + c * 16, vthg + (size_t)r * NTOK + (T0) + c * 8); \
        }                                                                                \
        cpa_commit();                                                                    \
    } while (0)

    LOAD_STAGE(0, tstart);

    float oacc[16][4];
#pragma unroll
    for (int i = 0; i < 16; i++)
#pragma unroll
        for (int j = 0; j < 4; j++) oacc[i][j] = 0.f;
    float rs0 = 0.f, rs1 = 0.f, m0 = MINIT, m1 = MINIT;

    int stage = 0;
    for (int it = 0; it < ntiles; it++) {
        const int t0 = tstart + it * 64;
        // prefetch next tile into the other stage, then wait for current
        if (it + 1 < ntiles) {
            LOAD_STAGE(stage ^ 1, t0 + 64);
            cpa_wait<1>();
        } else {
            cpa_wait<0>();
        }
        __syncthreads();

        const uint32_t koff = kbase + stage * STG_SZ;
        const uint32_t voff = vbase + stage * STG_SZ;

        // adjacency prefetch (hidden under S-MMA)
        int2 av0[8], av1[8];
#pragma unroll
        for (int nb = 0; nb < 8; nb++) {
            const int col = t0 + nb * 8 + cq;
            av0[nb] = *(const int2*)(adj + (size_t)r0g * NTOK + col);
            av1[nb] = *(const int2*)(adj + (size_t)r1g * NTOK + col);
        }

        // ---- S = Q K^T (3-term bf16 split) ----
        float sacc[8][4];
#pragma unroll
        for (int i = 0; i < 8; i++)
#pragma unroll
            for (int j = 0; j < 4; j++) sacc[i][j] = 0.f;

#pragma unroll
        for (int kc = 0; kc < 8; kc++) {
            uint32_t qh[4], ql[4];
            ldm4(qoff + kc * 32, qh);
            ldm4(qoff + (QL_OFF - QH_OFF) + kc * 32, ql);
#pragma unroll
            for (int nb2 = 0; nb2 < 4; nb2++) {
                uint32_t kh[4], kl[4];
                ldm4(koff + nb2 * 16 * KPAD + kc * 32, kh);
                ldm4(koff + SK_L + nb2 * 16 * KPAD + kc * 32, kl);
                mma_bf16(sacc[2 * nb2],     qh[0], qh[1], qh[2], qh[3], kh[0], kh[2]);
                mma_bf16(sacc[2 * nb2 + 1], qh[0], qh[1], qh[2], qh[3], kh[1], kh[3]);
                mma_bf16(sacc[2 * nb2],     qh[0], qh[1], qh[2], qh[3], kl[0], kl[2]);
                mma_bf16(sacc[2 * nb2 + 1], qh[0], qh[1], qh[2], qh[3], kl[1], kl[3]);
                mma_bf16(sacc[2 * nb2],     ql[0], ql[1], ql[2], ql[3], kh[0], kh[2]);
                mma_bf16(sacc[2 * nb2 + 1], ql[0], ql[1], ql[2], ql[3], kh[1], kh[3]);
            }
        }

        // ---- mask first, then online max ----
#pragma unroll
        for (int nb = 0; nb < 8; nb++) {
            if (av0[nb].x <= 0) sacc[nb][0] = MNEG;
            if (av0[nb].y <= 0) sacc[nb][1] = MNEG;
            if (av1[nb].x <= 0) sacc[nb][2] = MNEG;
            if (av1[nb].y <= 0) sacc[nb][3] = MNEG;
        }
        float tm0 = MNEG, tm1 = MNEG;
#pragma unroll
        for (int nb = 0; nb < 8; nb++) {
            tm0 = fmaxf(tm0, fmaxf(sacc[nb][0], sacc[nb][1]));
            tm1 = fmaxf(tm1, fmaxf(sacc[nb][2], sacc[nb][3]));
        }
        tm0 = fmaxf(tm0, __shfl_xor_sync(0xffffffff, tm0, 1));
        tm0 = fmaxf(tm0, __shfl_xor_sync(0xffffffff, tm0, 2));
        tm1 = fmaxf(tm1, __shfl_xor_sync(0xffffffff, tm1, 1));
        tm1 = fmaxf(tm1, __shfl_xor_sync(0xffffffff, tm1, 2));
        if (tm0 > m0) {
            const float f = __expf(m0 - tm0);
            rs0 *= f;
#pragma unroll
            for (int db = 0; db < 16; db++) { oacc[db][0] *= f; oacc[db][1] *= f; }
            m0 = tm0;
        }
        if (tm1 > m1) {
            const float f = __expf(m1 - tm1);
            rs1 *= f;
#pragma unroll
            for (int db = 0; db < 16; db++) { oacc[db][2] *= f; oacc[db][3] *= f; }
            m1 = tm1;
        }

        // ---- exp -> fp16 P; row-sum of the ROUNDED p-hat (self-consistent) ----
        uint32_t ph[8][2];
#pragma unroll
        for (int nb = 0; nb < 8; nb++) {
            float p00 = __expf(sacc[nb][0] - m0);
            float p01 = __expf(sacc[nb][1] - m0);
            float p10 = __expf(sacc[nb][2] - m1);
            float p11 = __expf(sacc[nb][3] - m1);
            __half2 h0 = __floats2half2_rn(p00, p01);
            __half2 h1 = __floats2half2_rn(p10, p11);
            ph[nb][0] = *(uint32_t*)&h0;
            ph[nb][1] = *(uint32_t*)&h1;
            float2 f0 = __half22float2(h0), f1 = __half22float2(h1);
            rs0 += f0.x + f0.y;
            rs1 += f1.x + f1.y;
        }

        // ---- O += Ph Vh (single-term PV) ----
#pragma unroll
        for (int kc2 = 0; kc2 < 4; kc2++) {
            const uint32_t a0 = ph[2 * kc2][0], a1 = ph[2 * kc2][1];
            const uint32_t a2 = ph[2 * kc2 + 1][0], a3 = ph[2 * kc2 + 1][1];
#pragma unroll
            for (int db2 = 0; db2 < 8; db2++) {
                uint32_t vh[4];
                ldm4(voff + db2 * 16 * VPAD + kc2 * 32, vh);
                mma_f16(oacc[2 * db2],     a0, a1, a2, a3, vh[0], vh[2]);
                mma_f16(oacc[2 * db2 + 1], a0, a1, a2, a3, vh[1], vh[3]);
            }
        }
        __syncthreads();   // stage consumed; next iter may overwrite it
        stage ^= 1;
    }

    // ---- epilogue ----
    rs0 += __shfl_xor_sync(0xffffffff, rs0, 1);
    rs0 += __shfl_xor_sync(0xffffffff, rs0, 2);
    rs1 += __shfl_xor_sync(0xffffffff, rs1, 1);
    rs1 += __shfl_xor_sync(0xffffffff, rs1, 2);
    if ((lid & 3) == 0) {
        lp[(size_t)split * 2 * NTOK + r0g] = rs0;
        lp[(size_t)split * 2 * NTOK + NTOK + r0g] = m0;
        lp[(size_t)split * 2 * NTOK + r1g] = rs1;
        lp[(size_t)split * 2 * NTOK + NTOK + r1g] = m1;
    }
    float* mp0 = mp + ((size_t)split * NTOK + r0g) * DH;
    float* mp1 = mp + ((size_t)split * NTOK + r1g) * DH;
#pragma unroll
    for (int db = 0; db < 16; db++) {
        const int c = db * 8 + cq;
        *(float2*)(mp0 + c) = make_float2(oacc[db][0], oacc[db][1]);
        *(float2*)(mp1 + c) = make_float2(oacc[db][2], oacc[db][3]);
    }
}

// ---------------- combine splits (log-sum-exp merge) ----------------
__global__ void __launch_bounds__(256) combine_kernel(
    const float* __restrict__ mp, const float* __restrict__ lp, float* __restrict__ out)
{
    const int idx = blockIdx.x * 256 + threadIdx.x;
    const int row = idx >> 7;
    const float l0 = lp[row], mm0 = lp[NTOK + row];
    const float l1 = lp[2 * NTOK + row], mm1 = lp[3 * NTOK + row];
    const float M = fmaxf(mm0, mm1);
    const float e0 = __expf(mm0 - M), e1 = __expf(mm1 - M);
    out[idx] = (mp[idx] * e0 + mp[NTOK * DH + idx] * e1) / (l0 * e0 + l1 * e1);
}

// ---------------- fp32 GEMM (QKV + MLP) ----------------
__global__ void __launch_bounds__(256) gemm2_kernel(
    const float* __restrict__ A, const float* __restrict__ W,
    const float* __restrict__ bias, float* __restrict__ C, int relu)
{
    extern __shared__ float smf[];
    float* As = smf;
    float* Ws = smf + 64 * 128;
    const int tid = threadIdx.x;
    const int tx = tid & 15, ty = tid >> 4;
    const int r0 = blockIdx.x * 64;

    for (int idx = tid; idx < 64 * 32; idx += 256) {
        int row = idx >> 5, f4 = idx & 31;
        ((float4*)(As + row * 128))[f4] = ((const float4*)(A + (size_t)(r0 + row) * 128))[f4];
    }
    for (int idx = tid; idx < 128 * 32; idx += 256) {
        int row = idx >> 5, f4 = idx & 31;
        ((float4*)(Ws + row * 128))[f4] = ((const float4*)(W + row * 128))[f4];
    }
    __syncthreads();

    float acc[4][8];
#pragma unroll
    for (int i = 0; i < 4; i++)
#pragma unroll
        for (int j = 0; j < 8; j++) acc[i][j] = 0.f;

#pragma unroll 4
    for (int kk = 0; kk < 128; kk++) {
        float a0 = As[(ty * 4 + 0) * 128 + kk];
        float a1 = As[(ty * 4 + 1) * 128 + kk];
        float a2 = As[(ty * 4 + 2) * 128 + kk];
        float a3 = As[(ty * 4 + 3) * 128 + kk];
        float4 w0 = ((float4*)(Ws + kk * 128))[tx * 2];
        float4 w1 = ((float4*)(Ws + kk * 128))[tx * 2 + 1];
        acc[0][0] += a0 * w0.x; acc[0][1] += a0 * w0.y; acc[0][2] += a0 * w0.z; acc[0][3] += a0 * w0.w;
        acc[0][4] += a0 * w1.x; acc[0][5] += a0 * w1.y; acc[0][6] += a0 * w1.z; acc[0][7] += a0 * w1.w;
        acc[1][0] += a1 * w0.x; acc[1][1] += a1 * w0.y; acc[1][2] += a1 * w0.z; acc[1][3] += a1 * w0.w;
        acc[1][4] += a1 * w1.x; acc[1][5] += a1 * w1.y; acc[1][6] += a1 * w1.z; acc[1][7] += a1 * w1.w;
        acc[2][0] += a2 * w0.x; acc[2][1] += a2 * w0.y; acc[2][2] += a2 * w0.z; acc[2][3] += a2 * w0.w;
        acc[2][4] += a2 * w1.x; acc[2][5] += a2 * w1.y; acc[2][6] += a2 * w1.z; acc[2][7] += a2 * w1.w;
        acc[3][0] += a3 * w0.x; acc[3][1] += a3 * w0.y; acc[3][2] += a3 * w0.z; acc[3][3] += a3 * w0.w;
        acc[3][4] += a3 * w1.x; acc[3][5] += a3 * w1.y; acc[3][6] += a3 * w1.z; acc[3][7] += a3 * w1.w;
    }

#pragma unroll
    for (int i = 0; i < 4; i++) {
        float* crow = C + (size_t)(r0 + ty * 4 + i) * 128 + tx * 8;
#pragma unroll
        for (int j = 0; j < 8; j++) {
            float v = acc[i][j] + (bias ? bias[tx * 8 + j] : 0.f);
            if (relu) v = fmaxf(v, 0.f);
            crow[j] = v;
        }
    }
}

// ---------------- launch ----------------
extern "C" void kernel_launch(void* const* d_in, const int* in_sizes, int n_in,
                              void* d_out, int out_size)
{
    const float* H   = (const float*)d_in[0];
    const int*   adj = (const int*)d_in[1];
    const float* Wq  = (const float*)d_in[2];
    const float* Wk  = (const float*)d_in[3];
    const float* Wv  = (const float*)d_in[4];
    const float* W1  = (const float*)d_in[5];
    const float* b1  = (const float*)d_in[6];
    const float* W2  = (const float*)d_in[7];
    const float* b2  = (const float*)d_in[8];
    float* out = (float*)d_out;

    float *q, *k, *v, *mpd, *lpd, *m, *h;
    __nv_bfloat16 *qh, *ql, *kh, *kl;
    __half *vth;
    cudaGetSymbolAddress((void**)&q,   g_q);
    cudaGetSymbolAddress((void**)&k,   g_k);
    cudaGetSymbolAddress((void**)&v,   g_v);
    cudaGetSymbolAddress((void**)&qh,  g_qh);
    cudaGetSymbolAddress((void**)&ql,  g_ql);
    cudaGetSymbolAddress((void**)&kh,  g_kh);
    cudaGetSymbolAddress((void**)&kl,  g_kl);
    cudaGetSymbolAddress((void**)&vth, g_vth);
    cudaGetSymbolAddress((void**)&mpd, g_mp);
    cudaGetSymbolAddress((void**)&lpd, g_lp);
    cudaGetSymbolAddress((void**)&m,   g_m);
    cudaGetSymbolAddress((void**)&h,   g_h);

    cudaFuncSetAttribute(attn_kernel, cudaFuncAttributeMaxDynamicSharedMemorySize, ATT_SMEM);
    cudaFuncSetAttribute(gemm2_kernel, cudaFuncAttributeMaxDynamicSharedMemorySize, 96 * 1024);

    const int gsm = 96 * 1024;
    gemm2_kernel<<<NTOK / 64, 256, gsm>>>(H, Wq, nullptr, q, 0);
    gemm2_kernel<<<NTOK / 64, 256, gsm>>>(H, Wk, nullptr, k, 0);
    gemm2_kernel<<<NTOK / 64, 256, gsm>>>(H, Wv, nullptr, v, 0);

    qkconv_kernel<<<dim3(NTOK * DH / 4 / 256, 2), 256>>>(q, k, qh, ql, kh, kl);
    vtconv_kernel<<<dim3(NTOK / 32, DH / 32), 256>>>(v, vth);

    attn_kernel<<<dim3(NTOK / 128, 2), 256, ATT_SMEM>>>(qh, ql, kh, kl, vth,
                                                        adj, mpd, lpd);

    combine_kernel<<<NTOK * DH / 256, 256>>>(mpd, lpd, m);

    gemm2_kernel<<<NTOK / 64, 256, gsm>>>(m, W1, b1, h, 1);
    gemm2_kernel<<<NTOK / 64, 256, gsm>>>(h, W2, b2, out, 1);
}

// round 9
// speedup vs baseline: 5.1064x; 1.0599x over previous
#include <cuda_runtime.h>
#include <cuda_bf16.h>
#include <cuda_fp16.h>
#include <cstdint>

#define NTOK 8192
#define DH   128

// ---------------- scratch ----------------
__device__ __nv_bfloat16 g_qh[NTOK * DH];
__device__ __nv_bfloat16 g_ql[NTOK * DH];
__device__ __nv_bfloat16 g_kh[NTOK * DH];
__device__ __nv_bfloat16 g_kl[NTOK * DH];
__device__ __half g_vth[DH * NTOK];
__device__ float g_mp[2 * NTOK * DH];
__device__ float g_lp[4 * NTOK];       // [split][rs | m][row]
__device__ float g_h[NTOK * DH];

// ---------------- helpers ----------------
__device__ __forceinline__ uint32_t smem_u32(const void* p) {
    uint32_t a;
    asm("{ .reg .u64 t; cvta.to.shared.u64 t, %1; cvt.u32.u64 %0, t; }" : "=r"(a) : "l"(p));
    return a;
}
__device__ __forceinline__ void cpa16(uint32_t dst, const void* src) {
    asm volatile("cp.async.cg.shared.global [%0], [%1], 16;" :: "r"(dst), "l"(src));
}
__device__ __forceinline__ void cpa_commit() {
    asm volatile("cp.async.commit_group;" ::: "memory");
}
template <int N>
__device__ __forceinline__ void cpa_wait() {
    asm volatile("cp.async.wait_group %0;" :: "n"(N) : "memory");
}
__device__ __forceinline__ void ldm4(uint32_t addr, uint32_t r[4]) {
    asm volatile("ldmatrix.sync.aligned.m8n8.x4.shared.b16 {%0,%1,%2,%3}, [%4];"
                 : "=r"(r[0]), "=r"(r[1]), "=r"(r[2]), "=r"(r[3]) : "r"(addr));
}
__device__ __forceinline__ void mma_bf16(float c[4], uint32_t a0, uint32_t a1,
                                         uint32_t a2, uint32_t a3,
                                         uint32_t b0, uint32_t b1) {
    asm volatile("mma.sync.aligned.m16n8k16.row.col.f32.bf16.bf16.f32 "
                 "{%0,%1,%2,%3}, {%4,%5,%6,%7}, {%8,%9}, {%0,%1,%2,%3};"
                 : "+f"(c[0]), "+f"(c[1]), "+f"(c[2]), "+f"(c[3])
                 : "r"(a0), "r"(a1), "r"(a2), "r"(a3), "r"(b0), "r"(b1));
}
__device__ __forceinline__ void mma_f16(float c[4], uint32_t a0, uint32_t a1,
                                        uint32_t a2, uint32_t a3,
                                        uint32_t b0, uint32_t b1) {
    asm volatile("mma.sync.aligned.m16n8k16.row.col.f32.f16.f16.f32 "
                 "{%0,%1,%2,%3}, {%4,%5,%6,%7}, {%8,%9}, {%0,%1,%2,%3};"
                 : "+f"(c[0]), "+f"(c[1]), "+f"(c[2]), "+f"(c[3])
                 : "r"(a0), "r"(a1), "r"(a2), "r"(a3), "r"(b0), "r"(b1));
}
__device__ __forceinline__ uint32_t pkbf(float a, float b) {
    __nv_bfloat162 t = __floats2bfloat162_rn(a, b);
    return *reinterpret_cast<uint32_t*>(&t);
}

// ---------------- fused QKV + convert ----------------
// grid 128, block 256: 64 rows/CTA. Reads H tile once, loops over Wq/Wk/Wv,
// writes q/k as bf16 hi+lo and v as transposed fp16.
__global__ void __launch_bounds__(256) qkv_kernel(
    const float* __restrict__ H,
    const float* __restrict__ Wq, const float* __restrict__ Wk, const float* __restrict__ Wv,
    __nv_bfloat16* __restrict__ qh, __nv_bfloat16* __restrict__ ql,
    __nv_bfloat16* __restrict__ kh, __nv_bfloat16* __restrict__ kl,
    __half* __restrict__ vth)
{
    extern __shared__ float smf[];
    float* As = smf;            // [64][128]
    float* Ws = smf + 64 * 128; // [128][128]
    const int tid = threadIdx.x;
    const int tx = tid & 15, ty = tid >> 4;
    const int r0 = blockIdx.x * 64;

    for (int idx = tid; idx < 64 * 32; idx += 256) {
        int row = idx >> 5, f4 = idx & 31;
        ((float4*)(As + row * 128))[f4] = ((const float4*)(H + (size_t)(r0 + row) * 128))[f4];
    }

    const float* wsrc[3] = {Wq, Wk, Wv};
    for (int w = 0; w < 3; w++) {
        __syncthreads();   // protect Ws from previous iter readers
        for (int idx = tid; idx < 128 * 32; idx += 256) {
            int row = idx >> 5, f4 = idx & 31;
            ((float4*)(Ws + row * 128))[f4] = ((const float4*)(wsrc[w] + row * 128))[f4];
        }
        __syncthreads();

        float acc[4][8];
#pragma unroll
        for (int i = 0; i < 4; i++)
#pragma unroll
            for (int j = 0; j < 8; j++) acc[i][j] = 0.f;

#pragma unroll 4
        for (int kk = 0; kk < 128; kk++) {
            float a0 = As[(ty * 4 + 0) * 128 + kk];
            float a1 = As[(ty * 4 + 1) * 128 + kk];
            float a2 = As[(ty * 4 + 2) * 128 + kk];
            float a3 = As[(ty * 4 + 3) * 128 + kk];
            float4 w0 = ((float4*)(Ws + kk * 128))[tx * 2];
            float4 w1 = ((float4*)(Ws + kk * 128))[tx * 2 + 1];
            acc[0][0] += a0 * w0.x; acc[0][1] += a0 * w0.y; acc[0][2] += a0 * w0.z; acc[0][3] += a0 * w0.w;
            acc[0][4] += a0 * w1.x; acc[0][5] += a0 * w1.y; acc[0][6] += a0 * w1.z; acc[0][7] += a0 * w1.w;
            acc[1][0] += a1 * w0.x; acc[1][1] += a1 * w0.y; acc[1][2] += a1 * w0.z; acc[1][3] += a1 * w0.w;
            acc[1][4] += a1 * w1.x; acc[1][5] += a1 * w1.y; acc[1][6] += a1 * w1.z; acc[1][7] += a1 * w1.w;
            acc[2][0] += a2 * w0.x; acc[2][1] += a2 * w0.y; acc[2][2] += a2 * w0.z; acc[2][3] += a2 * w0.w;
            acc[2][4] += a2 * w1.x; acc[2][5] += a2 * w1.y; acc[2][6] += a2 * w1.z; acc[2][7] += a2 * w1.w;
            acc[3][0] += a3 * w0.x; acc[3][1] += a3 * w0.y; acc[3][2] += a3 * w0.z; acc[3][3] += a3 * w0.w;
            acc[3][4] += a3 * w1.x; acc[3][5] += a3 * w1.y; acc[3][6] += a3 * w1.z; acc[3][7] += a3 * w1.w;
        }

        if (w < 2) {
            __nv_bfloat16* dh = (w == 0) ? qh : kh;
            __nv_bfloat16* dl = (w == 0) ? ql : kl;
#pragma unroll
            for (int i = 0; i < 4; i++) {
                uint32_t hv[4], lv[4];
#pragma unroll
                for (int j = 0; j < 4; j++) {
                    float v0 = acc[i][2 * j], v1 = acc[i][2 * j + 1];
                    __nv_bfloat16 h0 = __float2bfloat16(v0), h1 = __float2bfloat16(v1);
                    __nv_bfloat162 hp = __halves2bfloat162(h0, h1);
                    hv[j] = *(uint32_t*)&hp;
                    lv[j] = pkbf(v0 - __bfloat162float(h0), v1 - __bfloat162float(h1));
                }
                const size_t off = (size_t)(r0 + ty * 4 + i) * DH + tx * 8;
                *(uint4*)(dh + off) = make_uint4(hv[0], hv[1], hv[2], hv[3]);
                *(uint4*)(dl + off) = make_uint4(lv[0], lv[1], lv[2], lv[3]);
            }
        } else {
            // V: fp16, transposed [d][t]; 4 consecutive t per (col) -> 8B stores
#pragma unroll
            for (int j = 0; j < 8; j++) {
                __half2 p0 = __floats2half2_rn(acc[0][j], acc[1][j]);
                __half2 p1 = __floats2half2_rn(acc[2][j], acc[3][j]);
                *(uint2*)(vth + (size_t)(tx * 8 + j) * NTOK + r0 + ty * 4) =
                    make_uint2(*(uint32_t*)&p0, *(uint32_t*)&p1);
            }
        }
    }
}

// ---------------- fused attention ----------------
// 128 CTAs (64 q-tiles x 2 splits), 256 threads, 128 q-rows/CTA, BN=64,
// Q fragments in registers, 3-stage K/V pipeline.
#define KPAD 272
#define VPAD 144
#define STG_SZ 53248              // KH(17408)+KL(17408)+VH(18432)
#define SK_L   17408
#define SV_H   34816
#define ATT_SMEM (3 * STG_SZ)     // 159744
#define MNEG  -1e30f
#define MINIT -1e29f

__global__ void __launch_bounds__(256, 1) attn_kernel(
    const __nv_bfloat16* __restrict__ qhg, const __nv_bfloat16* __restrict__ qlg,
    const __nv_bfloat16* __restrict__ khg, const __nv_bfloat16* __restrict__ klg,
    const __half* __restrict__ vthg,
    const int* __restrict__ adj, float* __restrict__ mp, float* __restrict__ lp)
{
    extern __shared__ char smc[];
    const uint32_t sb = smem_u32(smc);
    const int tid = threadIdx.x;
    const int wid = tid >> 5, lid = tid & 31;
    const int wrow = wid * 16;
    const int qbase = blockIdx.x * 128;
    const int split = blockIdx.y;
    const int tstart = split * (NTOK / 2);
    const int ntiles = (NTOK / 2) / 64;

    const int lrow = lid & 15, lcol = (lid >> 4) * 8;
    const uint32_t kbase = sb + lrow * KPAD + lcol * 2;          // + stage*STG_SZ (+SK_L)
    const uint32_t vbase = sb + SV_H + lrow * VPAD + lcol * 2;

    const int fr0 = wrow + (lid >> 2);
    const int r0g = qbase + fr0;
    const int r1g = r0g + 8;
    const int cq = 2 * (lid & 3);

    // ---- prologue: pull Q hi then Q lo through stage0, keep fragments in regs ----
    uint32_t qfh[8][4], qfl[8][4];
    {
        const uint32_t qoff = sb + (wrow + lrow) * KPAD + lcol * 2;
        // Q hi
#pragma unroll
        for (int i = 0; i < 8; i++) {
            const int idx = tid + i * 256;
            const int r = idx >> 4, c = idx & 15;
            cpa16(sb + r * KPAD + c * 16, qhg + (size_t)(qbase + r) * DH + c * 8);
        }
        cpa_commit(); cpa_wait<0>(); __syncthreads();
#pragma unroll
        for (int kc = 0; kc < 8; kc++) ldm4(qoff + kc * 32, qfh[kc]);
        __syncthreads();
        // Q lo
#pragma unroll
        for (int i = 0; i < 8; i++) {
            const int idx = tid + i * 256;
            const int r = idx >> 4, c = idx & 15;
            cpa16(sb + r * KPAD + c * 16, qlg + (size_t)(qbase + r) * DH + c * 8);
        }
        cpa_commit(); cpa_wait<0>(); __syncthreads();
#pragma unroll
        for (int kc = 0; kc < 8; kc++) ldm4(qoff + kc * 32, qfl[kc]);
        __syncthreads();
    }

#define LOAD_STAGE(stg, T0)                                                              \
    do {                                                                                 \
        const uint32_t sbase = sb + (stg) * STG_SZ;                                      \
        _Pragma("unroll")                                                                \
        for (int i = 0; i < 4; i++) {                                                    \
            const int idx = tid + i * 256;                                               \
            const int r = idx >> 4, c = idx & 15;                                        \
            cpa16(sbase + r * KPAD + c * 16,        khg + (size_t)((T0) + r) * DH + c * 8); \
            cpa16(sbase + SK_L + r * KPAD + c * 16, klg + (size_t)((T0) + r) * DH + c * 8); \
        }                                                                                \
        _Pragma("unroll")                                                                \
        for (int i = 0; i < 4; i++) {                                                    \
            const int idx = tid + i * 256;                                               \
            const int r = idx >> 3, c = idx & 7;                                         \
            cpa16(sbase + SV_H + r * VPAD + c * 16, vthg + (size_t)r * NTOK + (T0) + c * 8); \
        }                                                                                \
        cpa_commit();                                                                    \
    } while (0)

    LOAD_STAGE(0, tstart);
    LOAD_STAGE(1, tstart + 64);

    float oacc[16][4];
#pragma unroll
    for (int i = 0; i < 16; i++)
#pragma unroll
        for (int j = 0; j < 4; j++) oacc[i][j] = 0.f;
    float rs0 = 0.f, rs1 = 0.f, m0 = MINIT, m1 = MINIT;

    int stage = 0;
    for (int it = 0; it < ntiles; it++) {
        const int t0 = tstart + it * 64;

        // adjacency loads first (DRAM latency overlaps stage wait)
        int2 av0[8], av1[8];
#pragma unroll
        for (int nb = 0; nb < 8; nb++) {
            const int col = t0 + nb * 8 + cq;
            av0[nb] = *(const int2*)(adj + (size_t)r0g * NTOK + col);
            av1[nb] = *(const int2*)(adj + (size_t)r1g * NTOK + col);
        }

        if (it + 2 < ntiles) { LOAD_STAGE((it + 2) % 3, t0 + 128); cpa_wait<2>(); }
        else if (it + 1 < ntiles) cpa_wait<1>();
        else cpa_wait<0>();
        __syncthreads();

        // compress adjacency into one register (frees 30 regs for the MMA body)
        uint32_t mk = 0;
#pragma unroll
        for (int nb = 0; nb < 8; nb++) {
            mk |= (av0[nb].x > 0 ? 1u : 0u) << (2 * nb);
            mk |= (av0[nb].y > 0 ? 1u : 0u) << (2 * nb + 1);
            mk |= (av1[nb].x > 0 ? 1u : 0u) << (16 + 2 * nb);
            mk |= (av1[nb].y > 0 ? 1u : 0u) << (16 + 2 * nb + 1);
        }

        const uint32_t koff = kbase + stage * STG_SZ;
        const uint32_t voff = vbase + stage * STG_SZ;

        // ---- S = Q K^T (3-term bf16, Q from registers) ----
        float sacc[8][4];
#pragma unroll
        for (int i = 0; i < 8; i++)
#pragma unroll
            for (int j = 0; j < 4; j++) sacc[i][j] = 0.f;

#pragma unroll
        for (int kc = 0; kc < 8; kc++) {
#pragma unroll
            for (int nb2 = 0; nb2 < 4; nb2++) {
                uint32_t kh[4], kl[4];
                ldm4(koff + nb2 * 16 * KPAD + kc * 32, kh);
                ldm4(koff + SK_L + nb2 * 16 * KPAD + kc * 32, kl);
                mma_bf16(sacc[2 * nb2],     qfh[kc][0], qfh[kc][1], qfh[kc][2], qfh[kc][3], kh[0], kh[2]);
                mma_bf16(sacc[2 * nb2 + 1], qfh[kc][0], qfh[kc][1], qfh[kc][2], qfh[kc][3], kh[1], kh[3]);
                mma_bf16(sacc[2 * nb2],     qfh[kc][0], qfh[kc][1], qfh[kc][2], qfh[kc][3], kl[0], kl[2]);
                mma_bf16(sacc[2 * nb2 + 1], qfh[kc][0], qfh[kc][1], qfh[kc][2], qfh[kc][3], kl[1], kl[3]);
                mma_bf16(sacc[2 * nb2],     qfl[kc][0], qfl[kc][1], qfl[kc][2], qfl[kc][3], kh[0], kh[2]);
                mma_bf16(sacc[2 * nb2 + 1], qfl[kc][0], qfl[kc][1], qfl[kc][2], qfl[kc][3], kh[1], kh[3]);
            }
        }

        // ---- mask first (valid-only max), then online max ----
#pragma unroll
        for (int nb = 0; nb < 8; nb++) {
            if (!((mk >> (2 * nb)) & 1))      sacc[nb][0] = MNEG;
            if (!((mk >> (2 * nb + 1)) & 1))  sacc[nb][1] = MNEG;
            if (!((mk >> (16 + 2 * nb)) & 1)) sacc[nb][2] = MNEG;
            if (!((mk >> (17 + 2 * nb)) & 1)) sacc[nb][3] = MNEG;
        }
        float tm0 = MNEG, tm1 = MNEG;
#pragma unroll
        for (int nb = 0; nb < 8; nb++) {
            tm0 = fmaxf(tm0, fmaxf(sacc[nb][0], sacc[nb][1]));
            tm1 = fmaxf(tm1, fmaxf(sacc[nb][2], sacc[nb][3]));
        }
        tm0 = fmaxf(tm0, __shfl_xor_sync(0xffffffff, tm0, 1));
        tm0 = fmaxf(tm0, __shfl_xor_sync(0xffffffff, tm0, 2));
        tm1 = fmaxf(tm1, __shfl_xor_sync(0xffffffff, tm1, 1));
        tm1 = fmaxf(tm1, __shfl_xor_sync(0xffffffff, tm1, 2));
        if (tm0 > m0) {
            const float f = __expf(m0 - tm0);
            rs0 *= f;
#pragma unroll
            for (int db = 0; db < 16; db++) { oacc[db][0] *= f; oacc[db][1] *= f; }
            m0 = tm0;
        }
        if (tm1 > m1) {
            const float f = __expf(m1 - tm1);
            rs1 *= f;
#pragma unroll
            for (int db = 0; db < 16; db++) { oacc[db][2] *= f; oacc[db][3] *= f; }
            m1 = tm1;
        }

        // ---- exp -> fp16 P; row-sum of ROUNDED p-hat (self-consistent) ----
        uint32_t ph[8][2];
#pragma unroll
        for (int nb = 0; nb < 8; nb++) {
            float p00 = __expf(sacc[nb][0] - m0);
            float p01 = __expf(sacc[nb][1] - m0);
            float p10 = __expf(sacc[nb][2] - m1);
            float p11 = __expf(sacc[nb][3] - m1);
            __half2 h0 = __floats2half2_rn(p00, p01);
            __half2 h1 = __floats2half2_rn(p10, p11);
            ph[nb][0] = *(uint32_t*)&h0;
            ph[nb][1] = *(uint32_t*)&h1;
            float2 f0 = __half22float2(h0), f1 = __half22float2(h1);
            rs0 += f0.x + f0.y;
            rs1 += f1.x + f1.y;
        }

        // ---- O += Ph Vh ----
#pragma unroll
        for (int kc2 = 0; kc2 < 4; kc2++) {
            const uint32_t a0 = ph[2 * kc2][0], a1 = ph[2 * kc2][1];
            const uint32_t a2 = ph[2 * kc2 + 1][0], a3 = ph[2 * kc2 + 1][1];
#pragma unroll
            for (int db2 = 0; db2 < 8; db2++) {
                uint32_t vh[4];
                ldm4(voff + db2 * 16 * VPAD + kc2 * 32, vh);
                mma_f16(oacc[2 * db2],     a0, a1, a2, a3, vh[0], vh[2]);
                mma_f16(oacc[2 * db2 + 1], a0, a1, a2, a3, vh[1], vh[3]);
            }
        }
        __syncthreads();   // stage consumed; next iter's prefetch overwrites it
        stage = (stage + 1) % 3;
    }

    // ---- epilogue ----
    rs0 += __shfl_xor_sync(0xffffffff, rs0, 1);
    rs0 += __shfl_xor_sync(0xffffffff, rs0, 2);
    rs1 += __shfl_xor_sync(0xffffffff, rs1, 1);
    rs1 += __shfl_xor_sync(0xffffffff, rs1, 2);
    if ((lid & 3) == 0) {
        lp[(size_t)split * 2 * NTOK + r0g] = rs0;
        lp[(size_t)split * 2 * NTOK + NTOK + r0g] = m0;
        lp[(size_t)split * 2 * NTOK + r1g] = rs1;
        lp[(size_t)split * 2 * NTOK + NTOK + r1g] = m1;
    }
    float* mp0 = mp + ((size_t)split * NTOK + r0g) * DH;
    float* mp1 = mp + ((size_t)split * NTOK + r1g) * DH;
#pragma unroll
    for (int db = 0; db < 16; db++) {
        const int c = db * 8 + cq;
        *(float2*)(mp0 + c) = make_float2(oacc[db][0], oacc[db][1]);
        *(float2*)(mp1 + c) = make_float2(oacc[db][2], oacc[db][3]);
    }
}

// ---------------- MLP layer 1 with fused split-combine ----------------
__global__ void __launch_bounds__(256) mlp1_kernel(
    const float* __restrict__ mp, const float* __restrict__ lp,
    const float* __restrict__ W, const float* __restrict__ bias, float* __restrict__ C)
{
    extern __shared__ float smf[];
    float* As = smf;
    float* Ws = smf + 64 * 128;
    const int tid = threadIdx.x;
    const int tx = tid & 15, ty = tid >> 4;
    const int r0 = blockIdx.x * 64;

    for (int idx = tid; idx < 64 * 32; idx += 256) {
        int row = idx >> 5, f4 = idx & 31;
        const int gr = r0 + row;
        const float l0 = lp[gr], mm0 = lp[NTOK + gr];
        const float l1 = lp[2 * NTOK + gr], mm1 = lp[3 * NTOK + gr];
        const float M = fmaxf(mm0, mm1);
        const float e0 = __expf(mm0 - M), e1 = __expf(mm1 - M);
        const float inv = 1.f / (l0 * e0 + l1 * e1);
        float4 a = ((const float4*)(mp + (size_t)gr * 128))[f4];
        float4 b = ((const float4*)(mp + (size_t)(NTOK + gr) * 128))[f4];
        float4 r;
        r.x = (a.x * e0 + b.x * e1) * inv;
        r.y = (a.y * e0 + b.y * e1) * inv;
        r.z = (a.z * e0 + b.z * e1) * inv;
        r.w = (a.w * e0 + b.w * e1) * inv;
        ((float4*)(As + row * 128))[f4] = r;
    }
    for (int idx = tid; idx < 128 * 32; idx += 256) {
        int row = idx >> 5, f4 = idx & 31;
        ((float4*)(Ws + row * 128))[f4] = ((const float4*)(W + row * 128))[f4];
    }
    __syncthreads();

    float acc[4][8];
#pragma unroll
    for (int i = 0; i < 4; i++)
#pragma unroll
        for (int j = 0; j < 8; j++) acc[i][j] = 0.f;

#pragma unroll 4
    for (int kk = 0; kk < 128; kk++) {
        float a0 = As[(ty * 4 + 0) * 128 + kk];
        float a1 = As[(ty * 4 + 1) * 128 + kk];
        float a2 = As[(ty * 4 + 2) * 128 + kk];
        float a3 = As[(ty * 4 + 3) * 128 + kk];
        float4 w0 = ((float4*)(Ws + kk * 128))[tx * 2];
        float4 w1 = ((float4*)(Ws + kk * 128))[tx * 2 + 1];
        acc[0][0] += a0 * w0.x; acc[0][1] += a0 * w0.y; acc[0][2] += a0 * w0.z; acc[0][3] += a0 * w0.w;
        acc[0][4] += a0 * w1.x; acc[0][5] += a0 * w1.y; acc[0][6] += a0 * w1.z; acc[0][7] += a0 * w1.w;
        acc[1][0] += a1 * w0.x; acc[1][1] += a1 * w0.y; acc[1][2] += a1 * w0.z; acc[1][3] += a1 * w0.w;
        acc[1][4] += a1 * w1.x; acc[1][5] += a1 * w1.y; acc[1][6] += a1 * w1.z; acc[1][7] += a1 * w1.w;
        acc[2][0] += a2 * w0.x; acc[2][1] += a2 * w0.y; acc[2][2] += a2 * w0.z; acc[2][3] += a2 * w0.w;
        acc[2][4] += a2 * w1.x; acc[2][5] += a2 * w1.y; acc[2][6] += a2 * w1.z; acc[2][7] += a2 * w1.w;
        acc[3][0] += a3 * w0.x; acc[3][1] += a3 * w0.y; acc[3][2] += a3 * w0.z; acc[3][3] += a3 * w0.w;
        acc[3][4] += a3 * w1.x; acc[3][5] += a3 * w1.y; acc[3][6] += a3 * w1.z; acc[3][7] += a3 * w1.w;
    }

#pragma unroll
    for (int i = 0; i < 4; i++) {
        float* crow = C + (size_t)(r0 + ty * 4 + i) * 128 + tx * 8;
#pragma unroll
        for (int j = 0; j < 8; j++)
            crow[j] = fmaxf(acc[i][j] + bias[tx * 8 + j], 0.f);
    }
}

// ---------------- plain fp32 GEMM (final MLP layer) ----------------
__global__ void __launch_bounds__(256) gemm2_kernel(
    const float* __restrict__ A, const float* __restrict__ W,
    const float* __restrict__ bias, float* __restrict__ C, int relu)
{
    extern __shared__ float smf[];
    float* As = smf;
    float* Ws = smf + 64 * 128;
    const int tid = threadIdx.x;
    const int tx = tid & 15, ty = tid >> 4;
    const int r0 = blockIdx.x * 64;

    for (int idx = tid; idx < 64 * 32; idx += 256) {
        int row = idx >> 5, f4 = idx & 31;
        ((float4*)(As + row * 128))[f4] = ((const float4*)(A + (size_t)(r0 + row) * 128))[f4];
    }
    for (int idx = tid; idx < 128 * 32; idx += 256) {
        int row = idx >> 5, f4 = idx & 31;
        ((float4*)(Ws + row * 128))[f4] = ((const float4*)(W + row * 128))[f4];
    }
    __syncthreads();

    float acc[4][8];
#pragma unroll
    for (int i = 0; i < 4; i++)
#pragma unroll
        for (int j = 0; j < 8; j++) acc[i][j] = 0.f;

#pragma unroll 4
    for (int kk = 0; kk < 128; kk++) {
        float a0 = As[(ty * 4 + 0) * 128 + kk];
        float a1 = As[(ty * 4 + 1) * 128 + kk];
        float a2 = As[(ty * 4 + 2) * 128 + kk];
        float a3 = As[(ty * 4 + 3) * 128 + kk];
        float4 w0 = ((float4*)(Ws + kk * 128))[tx * 2];
        float4 w1 = ((float4*)(Ws + kk * 128))[tx * 2 + 1];
        acc[0][0] += a0 * w0.x; acc[0][1] += a0 * w0.y; acc[0][2] += a0 * w0.z; acc[0][3] += a0 * w0.w;
        acc[0][4] += a0 * w1.x; acc[0][5] += a0 * w1.y; acc[0][6] += a0 * w1.z; acc[0][7] += a0 * w1.w;
        acc[1][0] += a1 * w0.x; acc[1][1] += a1 * w0.y; acc[1][2] += a1 * w0.z; acc[1][3] += a1 * w0.w;
        acc[1][4] += a1 * w1.x; acc[1][5] += a1 * w1.y; acc[1][6] += a1 * w1.z; acc[1][7] += a1 * w1.w;
        acc[2][0] += a2 * w0.x; acc[2][1] += a2 * w0.y; acc[2][2] += a2 * w0.z; acc[2][3] += a2 * w0.w;
        acc[2][4] += a2 * w1.x; acc[2][5] += a2 * w1.y; acc[2][6] += a2 * w1.z; acc[2][7] += a2 * w1.w;
        acc[3][0] += a3 * w0.x; acc[3][1] += a3 * w0.y; acc[3][2] += a3 * w0.z; acc[3][3] += a3 * w0.w;
        acc[3][4] += a3 * w1.x; acc[3][5] += a3 * w1.y; acc[3][6] += a3 * w1.z; acc[3][7] += a3 * w1.w;
    }

#pragma unroll
    for (int i = 0; i < 4; i++) {
        float* crow = C + (size_t)(r0 + ty * 4 + i) * 128 + tx * 8;
#pragma unroll
        for (int j = 0; j < 8; j++) {
            float v = acc[i][j] + (bias ? bias[tx * 8 + j] : 0.f);
            if (relu) v = fmaxf(v, 0.f);
            crow[j] = v;
        }
    }
}

// ---------------- launch ----------------
extern "C" void kernel_launch(void* const* d_in, const int* in_sizes, int n_in,
                              void* d_out, int out_size)
{
    const float* H   = (const float*)d_in[0];
    const int*   adj = (const int*)d_in[1];
    const float* Wq  = (const float*)d_in[2];
    const float* Wk  = (const float*)d_in[3];
    const float* Wv  = (const float*)d_in[4];
    const float* W1  = (const float*)d_in[5];
    const float* b1  = (const float*)d_in[6];
    const float* W2  = (const float*)d_in[7];
    const float* b2  = (const float*)d_in[8];
    float* out = (float*)d_out;

    float *mpd, *lpd, *h;
    __nv_bfloat16 *qh, *ql, *kh, *kl;
    __half *vth;
    cudaGetSymbolAddress((void**)&qh,  g_qh);
    cudaGetSymbolAddress((void**)&ql,  g_ql);
    cudaGetSymbolAddress((void**)&kh,  g_kh);
    cudaGetSymbolAddress((void**)&kl,  g_kl);
    cudaGetSymbolAddress((void**)&vth, g_vth);
    cudaGetSymbolAddress((void**)&mpd, g_mp);
    cudaGetSymbolAddress((void**)&lpd, g_lp);
    cudaGetSymbolAddress((void**)&h,   g_h);

    cudaFuncSetAttribute(attn_kernel, cudaFuncAttributeMaxDynamicSharedMemorySize, ATT_SMEM);
    cudaFuncSetAttribute(qkv_kernel, cudaFuncAttributeMaxDynamicSharedMemorySize, 96 * 1024);
    cudaFuncSetAttribute(mlp1_kernel, cudaFuncAttributeMaxDynamicSharedMemorySize, 96 * 1024);
    cudaFuncSetAttribute(gemm2_kernel, cudaFuncAttributeMaxDynamicSharedMemorySize, 96 * 1024);

    const int gsm = 96 * 1024;
    qkv_kernel<<<NTOK / 64, 256, gsm>>>(H, Wq, Wk, Wv, qh, ql, kh, kl, vth);

    attn_kernel<<<dim3(NTOK / 128, 2), 256, ATT_SMEM>>>(qh, ql, kh, kl, vth,
                                                        adj, mpd, lpd);

    mlp1_kernel<<<NTOK / 64, 256, gsm>>>(mpd, lpd, W1, b1, h);
    gemm2_kernel<<<NTOK / 64, 256, gsm>>>(h, W2, b2, out, 1);
}